// round 8
// baseline (speedup 1.0000x reference)
#include <cuda_runtime.h>
#include <cuda_bf16.h>
#include <cstddef>

// ---------------------------------------------------------------------------
// SpatialGCN: 2-layer GCN, N=100000, E=800000, 128 -> 256 -> 128.
//
// Math reorder (exact up to fp rounding):
//   layer1: relu( agg(x) @ W1 + b1 )      [aggregate 128-dim BEFORE GEMM]
//   layer2: agg( h @ W2 ) + b2            [aggregate 128-dim AFTER GEMM]
// Aggregation uses a CSR built per launch (no float atomics in hot path).
// edge_index dtype (int64 in reference, possibly int32 after harness
// conversion) is detected ON DEVICE — no host sync, graph-capturable.
// ---------------------------------------------------------------------------

#define N_NODES 100000
#define N_EDGES 800000
#define IN_DIM 128
#define HID_DIM 256
#define OUT_DIM 128

// -------------------- device scratch (static, no allocs) -------------------
__device__ int   g_is64;                 // 1 if edge_index is int64
__device__ float g_deg[N_NODES];
__device__ float g_dis[N_NODES];
__device__ int   g_cnt[N_NODES];
__device__ int   g_off[N_NODES + 1];
__device__ int   g_cur[N_NODES];
__device__ int   g_csr_src[N_EDGES];
__device__ float g_csr_nrm[N_EDGES];
__device__ float g_aggx[(size_t)N_NODES * IN_DIM];   // agg(x); later reused as h2
__device__ float g_h[(size_t)N_NODES * HID_DIM];     // relu(layer1)

// ------------------------- edge-index access helpers ------------------------

__device__ __forceinline__ int edge_row(const void* ei, int e, int is64)
{
    if (is64) return (int)((const long long*)ei)[e];
    return ((const int*)ei)[e];
}
__device__ __forceinline__ int edge_col(const void* ei, int e, int is64)
{
    if (is64) return (int)((const long long*)ei)[N_EDGES + e];
    return ((const int*)ei)[N_EDGES + e];
}

// Detect dtype: interpret first 1024 entries of each half as int64.
// True int64 data: all in [0, N_NODES). int32 data reinterpreted: high word
// is a (random, almost surely nonzero) index -> huge value -> out of range.
__global__ void __launch_bounds__(256) k_detect(const void* ei)
{
    const long long* p = (const long long*)ei;
    int t = threadIdx.x;
    int ok = 1;
    for (int i = t; i < 1024; i += 256) {
        long long a = p[i];
        long long b = p[N_EDGES + i];
        if (a < 0 || a >= N_NODES || b < 0 || b >= N_NODES) ok = 0;
    }
    int all_ok = __syncthreads_and(ok);
    if (t == 0) g_is64 = all_ok;
}

// -------------------------------- kernels ----------------------------------

__global__ void k_init()
{
    int i = blockIdx.x * blockDim.x + threadIdx.x;
    if (i < N_NODES) { g_deg[i] = 0.f; g_cnt[i] = 0; }
}

__global__ void k_deg_count(const void* __restrict__ ei,
                            const float* __restrict__ w)
{
    int e = blockIdx.x * blockDim.x + threadIdx.x;
    if (e >= N_EDGES) return;
    int is64 = g_is64;
    int c = edge_col(ei, e, is64);
    atomicAdd(&g_deg[c], w[e]);
    atomicAdd(&g_cnt[c], 1);
}

__global__ void k_dis()
{
    int i = blockIdx.x * blockDim.x + threadIdx.x;
    if (i >= N_NODES) return;
    float d = g_deg[i];
    g_dis[i] = (d > 0.f) ? rsqrtf(d) : 0.f;
}

// Single-block exclusive scan of g_cnt -> g_off (and g_cur copy).
#define SCAN_T 1024
#define SCAN_CHUNK ((N_NODES + SCAN_T - 1) / SCAN_T)   // 98
__global__ void __launch_bounds__(SCAN_T) k_scan()
{
    __shared__ int s[SCAN_T];
    int t = threadIdx.x;
    int base = t * SCAN_CHUNK;
    int sum = 0;
    for (int i = 0; i < SCAN_CHUNK; i++) {
        int idx = base + i;
        if (idx < N_NODES) sum += g_cnt[idx];
    }
    s[t] = sum;
    __syncthreads();
    for (int off = 1; off < SCAN_T; off <<= 1) {
        int v = 0;
        if (t >= off) v = s[t - off];
        __syncthreads();
        s[t] += v;
        __syncthreads();
    }
    int run = (t == 0) ? 0 : s[t - 1];
    for (int i = 0; i < SCAN_CHUNK; i++) {
        int idx = base + i;
        if (idx < N_NODES) {
            g_off[idx] = run;
            g_cur[idx] = run;
            run += g_cnt[idx];
        }
    }
    if (t == 0) g_off[N_NODES] = s[SCAN_T - 1];
}

__global__ void k_place(const void* __restrict__ ei,
                        const float* __restrict__ w)
{
    int e = blockIdx.x * blockDim.x + threadIdx.x;
    if (e >= N_EDGES) return;
    int is64 = g_is64;
    int r = edge_row(ei, e, is64);
    int c = edge_col(ei, e, is64);
    float nm = g_dis[r] * w[e] * g_dis[c];
    int pos = atomicAdd(&g_cur[c], 1);
    g_csr_src[pos] = r;
    g_csr_nrm[pos] = nm;
}

// One warp per target node, 128-dim gather+weighted-sum, optional bias.
__device__ __forceinline__ void agg128_body(const float* __restrict__ src,
                                            float* __restrict__ dst,
                                            const float* __restrict__ bias)
{
    int gw = (blockIdx.x * blockDim.x + threadIdx.x) >> 5;
    if (gw >= N_NODES) return;
    int lane = threadIdx.x & 31;
    int beg = g_off[gw];
    int end = g_off[gw + 1];
    float4 acc = make_float4(0.f, 0.f, 0.f, 0.f);
    for (int e = beg; e < end; e++) {
        int   r  = g_csr_src[e];
        float nm = g_csr_nrm[e];
        float4 v = *(const float4*)(src + (size_t)r * 128 + lane * 4);
        acc.x = fmaf(nm, v.x, acc.x);
        acc.y = fmaf(nm, v.y, acc.y);
        acc.z = fmaf(nm, v.z, acc.z);
        acc.w = fmaf(nm, v.w, acc.w);
    }
    if (bias) {
        float4 bv = *(const float4*)(bias + lane * 4);
        acc.x += bv.x; acc.y += bv.y; acc.z += bv.z; acc.w += bv.w;
    }
    *(float4*)(dst + (size_t)gw * 128 + lane * 4) = acc;
}

// agg(x) -> g_aggx (no bias)
__global__ void k_agg_in(const float* __restrict__ x)
{
    agg128_body(x, g_aggx, nullptr);
}

// agg(g_aggx) + b2 -> out
__global__ void k_agg_out(float* __restrict__ out,
                          const float* __restrict__ b2)
{
    agg128_body(g_aggx, out, b2);
}

// Classic SIMT fp32 GEMM: C[M,N] = A[M,K] @ B[K,N] (+bias, optional relu).
// BM=BN=128, BK=8, 256 threads, 8x8 register tile per thread.
#define GBM 128
#define GBN 128
#define GBK 8
template <int DO_RELU, int HAS_BIAS>
__device__ __forceinline__ void sgemm_body(
    const float* __restrict__ A, const float* __restrict__ B,
    const float* __restrict__ bias, float* __restrict__ C,
    int M, int N, int K)
{
    __shared__ float As[GBK][GBM + 4];
    __shared__ float Bs[GBK][GBN];

    const int tid = threadIdx.x;
    const int bm = blockIdx.y * GBM;
    const int bn = blockIdx.x * GBN;
    const int ty = tid >> 4;        // 0..15
    const int tx = tid & 15;        // 0..15

    // A tile loader: 128 rows x 8 cols, float4 along K
    const int aRow = tid >> 1;           // 0..127
    const int aCol = (tid & 1) * 4;      // 0 or 4
    // B tile loader: 8 rows x 128 cols, float4 along N
    const int bRow = tid >> 5;           // 0..7
    const int bCol = (tid & 31) * 4;

    float acc[8][8];
#pragma unroll
    for (int i = 0; i < 8; i++)
#pragma unroll
        for (int j = 0; j < 8; j++) acc[i][j] = 0.f;

    for (int k0 = 0; k0 < K; k0 += GBK) {
        float4 av = make_float4(0.f, 0.f, 0.f, 0.f);
        if (bm + aRow < M)
            av = *(const float4*)(A + (size_t)(bm + aRow) * K + k0 + aCol);
        As[aCol + 0][aRow] = av.x;
        As[aCol + 1][aRow] = av.y;
        As[aCol + 2][aRow] = av.z;
        As[aCol + 3][aRow] = av.w;

        float4 bv = *(const float4*)(B + (size_t)(k0 + bRow) * N + bn + bCol);
        *(float4*)&Bs[bRow][bCol] = bv;

        __syncthreads();
#pragma unroll
        for (int k = 0; k < GBK; k++) {
            float ar[8], br[8];
#pragma unroll
            for (int i = 0; i < 8; i++) ar[i] = As[k][ty * 8 + i];
#pragma unroll
            for (int j = 0; j < 8; j++) br[j] = Bs[k][tx * 8 + j];
#pragma unroll
            for (int i = 0; i < 8; i++)
#pragma unroll
                for (int j = 0; j < 8; j++)
                    acc[i][j] = fmaf(ar[i], br[j], acc[i][j]);
        }
        __syncthreads();
    }

#pragma unroll
    for (int i = 0; i < 8; i++) {
        int row = bm + ty * 8 + i;
        if (row >= M) continue;
#pragma unroll
        for (int j = 0; j < 8; j += 4) {
            int col = bn + tx * 8 + j;
            float4 v = make_float4(acc[i][j], acc[i][j + 1],
                                   acc[i][j + 2], acc[i][j + 3]);
            if (HAS_BIAS) {
                v.x += bias[col];
                v.y += bias[col + 1];
                v.z += bias[col + 2];
                v.w += bias[col + 3];
            }
            if (DO_RELU) {
                v.x = fmaxf(v.x, 0.f);
                v.y = fmaxf(v.y, 0.f);
                v.z = fmaxf(v.z, 0.f);
                v.w = fmaxf(v.w, 0.f);
            }
            *(float4*)(C + (size_t)row * N + col) = v;
        }
    }
}

// layer 1: g_aggx[100000,128] @ W1[128,256] + b1, relu -> g_h
__global__ void __launch_bounds__(256) k_gemm1(const float* __restrict__ W1,
                                               const float* __restrict__ b1)
{
    sgemm_body<1, 1>(g_aggx, W1, b1, g_h, N_NODES, HID_DIM, IN_DIM);
}

// layer 2: g_h[100000,256] @ W2[256,128] -> g_aggx (reused as h2)
__global__ void __launch_bounds__(256) k_gemm2(const float* __restrict__ W2)
{
    sgemm_body<0, 0>(g_h, W2, nullptr, g_aggx, N_NODES, OUT_DIM, HID_DIM);
}

// -------------------------------- launcher ---------------------------------

extern "C" void kernel_launch(void* const* d_in, const int* in_sizes, int n_in,
                              void* d_out, int out_size)
{
    const float* x  = (const float*)d_in[0];
    const void*  ei = d_in[1];
    const float* w  = (const float*)d_in[2];
    const float* W1 = (const float*)d_in[3];
    const float* b1 = (const float*)d_in[4];
    const float* W2 = (const float*)d_in[5];
    const float* b2 = (const float*)d_in[6];
    float* out = (float*)d_out;

    const int nodeBlocks = (N_NODES + 255) / 256;
    const int edgeBlocks = (N_EDGES + 255) / 256;
    const int aggBlocks  = (N_NODES * 32 + 255) / 256;  // 1 warp / node
    const int mBlocks    = (N_NODES + GBM - 1) / GBM;   // 782

    // dtype detect + normalization + CSR build
    k_detect<<<1, 256>>>(ei);
    k_init<<<nodeBlocks, 256>>>();
    k_deg_count<<<edgeBlocks, 256>>>(ei, w);
    k_dis<<<nodeBlocks, 256>>>();
    k_scan<<<1, SCAN_T>>>();
    k_place<<<edgeBlocks, 256>>>(ei, w);

    // layer 1: agg(x) -> GEMM(+b1, relu) -> g_h
    k_agg_in<<<aggBlocks, 256>>>(x);
    {
        dim3 grid(HID_DIM / GBN, mBlocks);
        k_gemm1<<<grid, 256>>>(W1, b1);
    }

    // layer 2: GEMM -> g_aggx (reused) -> agg(+b2) -> out
    {
        dim3 grid(OUT_DIM / GBN, mBlocks);
        k_gemm2<<<grid, 256>>>(W2);
    }
    k_agg_out<<<aggBlocks, 256>>>(out, b2);
}

// round 10
// speedup vs baseline: 1.3546x; 1.3546x over previous
#include <cuda_runtime.h>
#include <cuda_bf16.h>
#include <cstddef>
#include <cstdint>

// ---------------------------------------------------------------------------
// SpatialGCN: 2-layer GCN, N=100000, E=800000, 128 -> 256 -> 128.
//   layer1: relu( agg(x) @ W1 + b1 )   [aggregate BEFORE GEMM, 128-dim]
//   layer2: agg( h @ W2 ) + b2         [aggregate AFTER GEMM, 128-dim]
// GEMMs: warp-level mma.sync m16n8k16 bf16 (base-target PTX, works at sm_103)
// with bf16 hi/lo split (AhBh + AhBl + AlBh, fp32 acc) for fp32 accuracy.
// CSR built per launch; edge_index dtype detected on device.
// ---------------------------------------------------------------------------

#define N_NODES 100000
#define N_EDGES 800000
#define IN_DIM 128
#define HID_DIM 256
#define OUT_DIM 128

typedef __nv_bfloat16 bf16;

// -------------------- device scratch (static, no allocs) -------------------
__device__ int   g_is64;
__device__ float g_deg[N_NODES];
__device__ float g_dis[N_NODES];
__device__ int   g_cnt[N_NODES];
__device__ int   g_off[N_NODES + 1];
__device__ int   g_cur[N_NODES];
__device__ int   g_csr_src[N_EDGES];
__device__ float g_csr_nrm[N_EDGES];

__device__ bf16  g_a1h[(size_t)N_NODES * IN_DIM];    // agg(x) hi
__device__ bf16  g_a1l[(size_t)N_NODES * IN_DIM];    // agg(x) lo
__device__ bf16  g_hh[(size_t)N_NODES * HID_DIM];    // relu(h) hi
__device__ bf16  g_hl[(size_t)N_NODES * HID_DIM];    // relu(h) lo
__device__ float g_h2[(size_t)N_NODES * OUT_DIM];    // h @ W2 (fp32)

// transposed + split weights: Wt[n][k], K contiguous
__device__ bf16  g_w1th[HID_DIM * IN_DIM];
__device__ bf16  g_w1tl[HID_DIM * IN_DIM];
__device__ bf16  g_w2th[OUT_DIM * HID_DIM];
__device__ bf16  g_w2tl[OUT_DIM * HID_DIM];

// ------------------------------ PTX helpers --------------------------------

__device__ __forceinline__ uint32_t smem_u32(const void* p)
{
    uint32_t a;
    asm("{ .reg .u64 t; cvta.to.shared.u64 t, %1; cvt.u32.u64 %0, t; }"
        : "=r"(a) : "l"(p));
    return a;
}

__device__ __forceinline__ void ldmx4(uint32_t& r0, uint32_t& r1,
                                      uint32_t& r2, uint32_t& r3, uint32_t a)
{
    asm volatile("ldmatrix.sync.aligned.m8n8.x4.shared.b16 {%0,%1,%2,%3}, [%4];"
                 : "=r"(r0), "=r"(r1), "=r"(r2), "=r"(r3) : "r"(a));
}

__device__ __forceinline__ void ldmx2(uint32_t& r0, uint32_t& r1, uint32_t a)
{
    asm volatile("ldmatrix.sync.aligned.m8n8.x2.shared.b16 {%0,%1}, [%2];"
                 : "=r"(r0), "=r"(r1) : "r"(a));
}

__device__ __forceinline__ void mma_bf16(float* d, const uint32_t* a,
                                         const uint32_t* b)
{
    asm volatile(
        "mma.sync.aligned.m16n8k16.row.col.f32.bf16.bf16.f32 "
        "{%0,%1,%2,%3}, {%4,%5,%6,%7}, {%8,%9}, {%0,%1,%2,%3};"
        : "+f"(d[0]), "+f"(d[1]), "+f"(d[2]), "+f"(d[3])
        : "r"(a[0]), "r"(a[1]), "r"(a[2]), "r"(a[3]), "r"(b[0]), "r"(b[1]));
}

// ------------------------- edge-index access helpers ------------------------

__device__ __forceinline__ int edge_row(const void* ei, int e, int is64)
{
    if (is64) return (int)((const long long*)ei)[e];
    return ((const int*)ei)[e];
}
__device__ __forceinline__ int edge_col(const void* ei, int e, int is64)
{
    if (is64) return (int)((const long long*)ei)[N_EDGES + e];
    return ((const int*)ei)[N_EDGES + e];
}

__global__ void __launch_bounds__(256) k_detect(const void* ei)
{
    const long long* p = (const long long*)ei;
    int t = threadIdx.x;
    int ok = 1;
    for (int i = t; i < 1024; i += 256) {
        long long a = p[i];
        long long b = p[N_EDGES + i];
        if (a < 0 || a >= N_NODES || b < 0 || b >= N_NODES) ok = 0;
    }
    int all_ok = __syncthreads_and(ok);
    if (t == 0) g_is64 = all_ok;
}

// ------------------------------ CSR pipeline -------------------------------

__global__ void k_init()
{
    int i = blockIdx.x * blockDim.x + threadIdx.x;
    if (i < N_NODES) { g_deg[i] = 0.f; g_cnt[i] = 0; }
}

__global__ void k_deg_count(const void* __restrict__ ei,
                            const float* __restrict__ w)
{
    int e = blockIdx.x * blockDim.x + threadIdx.x;
    if (e >= N_EDGES) return;
    int is64 = g_is64;
    int c = edge_col(ei, e, is64);
    atomicAdd(&g_deg[c], w[e]);
    atomicAdd(&g_cnt[c], 1);
}

__global__ void k_dis()
{
    int i = blockIdx.x * blockDim.x + threadIdx.x;
    if (i >= N_NODES) return;
    float d = g_deg[i];
    g_dis[i] = (d > 0.f) ? rsqrtf(d) : 0.f;
}

#define SCAN_T 1024
#define SCAN_CHUNK ((N_NODES + SCAN_T - 1) / SCAN_T)
__global__ void __launch_bounds__(SCAN_T) k_scan()
{
    __shared__ int s[SCAN_T];
    int t = threadIdx.x;
    int base = t * SCAN_CHUNK;
    int sum = 0;
    for (int i = 0; i < SCAN_CHUNK; i++) {
        int idx = base + i;
        if (idx < N_NODES) sum += g_cnt[idx];
    }
    s[t] = sum;
    __syncthreads();
    for (int off = 1; off < SCAN_T; off <<= 1) {
        int v = 0;
        if (t >= off) v = s[t - off];
        __syncthreads();
        s[t] += v;
        __syncthreads();
    }
    int run = (t == 0) ? 0 : s[t - 1];
    for (int i = 0; i < SCAN_CHUNK; i++) {
        int idx = base + i;
        if (idx < N_NODES) {
            g_off[idx] = run;
            g_cur[idx] = run;
            run += g_cnt[idx];
        }
    }
    if (t == 0) g_off[N_NODES] = s[SCAN_T - 1];
}

__global__ void k_place(const void* __restrict__ ei,
                        const float* __restrict__ w)
{
    int e = blockIdx.x * blockDim.x + threadIdx.x;
    if (e >= N_EDGES) return;
    int is64 = g_is64;
    int r = edge_row(ei, e, is64);
    int c = edge_col(ei, e, is64);
    float nm = g_dis[r] * w[e] * g_dis[c];
    int pos = atomicAdd(&g_cur[c], 1);
    g_csr_src[pos] = r;
    g_csr_nrm[pos] = nm;
}

// ----------------------------- aggregation ---------------------------------

__device__ __forceinline__ unsigned short bf_bits(bf16 h)
{
    return *(unsigned short*)&h;
}

// agg(x) -> bf16 hi/lo split (one warp per node)
__global__ void k_agg_in(const float* __restrict__ x)
{
    int gw = (blockIdx.x * blockDim.x + threadIdx.x) >> 5;
    if (gw >= N_NODES) return;
    int lane = threadIdx.x & 31;
    int beg = g_off[gw];
    int end = g_off[gw + 1];
    float4 acc = make_float4(0.f, 0.f, 0.f, 0.f);
    for (int e = beg; e < end; e++) {
        int   r  = g_csr_src[e];
        float nm = g_csr_nrm[e];
        float4 v = *(const float4*)(x + (size_t)r * 128 + lane * 4);
        acc.x = fmaf(nm, v.x, acc.x);
        acc.y = fmaf(nm, v.y, acc.y);
        acc.z = fmaf(nm, v.z, acc.z);
        acc.w = fmaf(nm, v.w, acc.w);
    }
    bf16 hx = __float2bfloat16(acc.x);
    bf16 hy = __float2bfloat16(acc.y);
    bf16 hz = __float2bfloat16(acc.z);
    bf16 hw = __float2bfloat16(acc.w);
    bf16 lx = __float2bfloat16(acc.x - __bfloat162float(hx));
    bf16 ly = __float2bfloat16(acc.y - __bfloat162float(hy));
    bf16 lz = __float2bfloat16(acc.z - __bfloat162float(hz));
    bf16 lw = __float2bfloat16(acc.w - __bfloat162float(hw));
    size_t o = (size_t)gw * 128 + lane * 4;
    *(ushort4*)(g_a1h + o) = make_ushort4(bf_bits(hx), bf_bits(hy), bf_bits(hz), bf_bits(hw));
    *(ushort4*)(g_a1l + o) = make_ushort4(bf_bits(lx), bf_bits(ly), bf_bits(lz), bf_bits(lw));
}

// agg(g_h2) + b2 -> out (fp32)
__global__ void k_agg_out(float* __restrict__ out,
                          const float* __restrict__ b2)
{
    int gw = (blockIdx.x * blockDim.x + threadIdx.x) >> 5;
    if (gw >= N_NODES) return;
    int lane = threadIdx.x & 31;
    int beg = g_off[gw];
    int end = g_off[gw + 1];
    float4 acc = make_float4(0.f, 0.f, 0.f, 0.f);
    for (int e = beg; e < end; e++) {
        int   r  = g_csr_src[e];
        float nm = g_csr_nrm[e];
        float4 v = *(const float4*)(g_h2 + (size_t)r * 128 + lane * 4);
        acc.x = fmaf(nm, v.x, acc.x);
        acc.y = fmaf(nm, v.y, acc.y);
        acc.z = fmaf(nm, v.z, acc.z);
        acc.w = fmaf(nm, v.w, acc.w);
    }
    float4 bv = *(const float4*)(b2 + lane * 4);
    acc.x += bv.x; acc.y += bv.y; acc.z += bv.z; acc.w += bv.w;
    *(float4*)(out + (size_t)gw * 128 + lane * 4) = acc;
}

// ---------------------------- weight prep ----------------------------------

__global__ void k_prep_w1(const float* __restrict__ W1)
{
    int i = blockIdx.x * blockDim.x + threadIdx.x;
    if (i >= IN_DIM * HID_DIM) return;
    int k = i / HID_DIM, n = i % HID_DIM;
    float v = W1[i];
    bf16 hi = __float2bfloat16(v);
    bf16 lo = __float2bfloat16(v - __bfloat162float(hi));
    g_w1th[n * IN_DIM + k] = hi;
    g_w1tl[n * IN_DIM + k] = lo;
}

__global__ void k_prep_w2(const float* __restrict__ W2)
{
    int i = blockIdx.x * blockDim.x + threadIdx.x;
    if (i >= HID_DIM * OUT_DIM) return;
    int k = i / OUT_DIM, n = i % OUT_DIM;
    float v = W2[i];
    bf16 hi = __float2bfloat16(v);
    bf16 lo = __float2bfloat16(v - __bfloat162float(hi));
    g_w2th[n * HID_DIM + k] = hi;
    g_w2tl[n * HID_DIM + k] = lo;
}

// ------------------------- mma.sync GEMM (bf16 split) -----------------------
// CTA tile 128x128, 256 threads = 8 warps (2 m x 4 n), warp tile 64x32.
// K staged in 128-wide smem tiles, padded rows (136 bf16 = 272B) for
// conflict-free ldmatrix. Accumulate AhBh + AhBl + AlBh in fp32 registers.

#define LDT 136
#define TILE_ELEMS (128 * LDT)
#define SM_AH_O 0
#define SM_AL_O (TILE_ELEMS)
#define SM_BH_O (2 * TILE_ELEMS)
#define SM_BL_O (3 * TILE_ELEMS)
#define SMEM_BYTES (4 * TILE_ELEMS * 2)   // 139264

// load 128 x 128 bf16 tile (rows beyond validRows zero-filled) into padded smem
__device__ __forceinline__ void load_tile(
    bf16* sm, uint32_t smo, const bf16* __restrict__ g,
    int rowStart, int validRows, int gStride, int kStart, int tid)
{
#pragma unroll
    for (int it = 0; it < 8; it++) {
        int c = it * 256 + tid;          // 2048 chunks of 8 bf16
        int r  = c >> 4;
        int cc = c & 15;
        uint4 v = make_uint4(0u, 0u, 0u, 0u);
        if (r < validRows)
            v = *(const uint4*)(g + (size_t)(rowStart + r) * gStride + kStart + cc * 8);
        *(uint4*)(sm + smo + r * LDT + cc * 8) = v;
    }
}

template <int KTILES, int SPLIT_OUT>
__device__ __forceinline__ void mma_gemm_body(
    const bf16* __restrict__ Ah, const bf16* __restrict__ Al,
    const bf16* __restrict__ Bh, const bf16* __restrict__ Bl,
    const float* __restrict__ bias,
    bf16* __restrict__ Ch, bf16* __restrict__ Cl,   // SPLIT_OUT=1
    float* __restrict__ Cf,                          // SPLIT_OUT=0
    int nTotal)
{
    extern __shared__ bf16 sm[];
    const int tid  = threadIdx.x;
    const int lane = tid & 31;
    const int wid  = tid >> 5;
    const int wm   = wid >> 2;          // 0..1
    const int wn   = wid & 3;           // 0..3
    const int mBase = blockIdx.x * 128;
    const int nBase = blockIdx.y * 128;
    const int validRows = min(128, N_NODES - mBase);
    const int KT = KTILES * 128;

    const uint32_t sbase = smem_u32(sm);

    float d[4][4][4];
#pragma unroll
    for (int i = 0; i < 4; i++)
#pragma unroll
        for (int j = 0; j < 4; j++)
#pragma unroll
            for (int r = 0; r < 4; r++) d[i][j][r] = 0.f;

    // per-thread ldmatrix address offsets (element units)
    const int aRow = (lane & 15);
    const int aK   = (lane >> 4) << 3;
    const int bRow = (lane & 7);
    const int bK   = ((lane >> 3) & 1) << 3;

    for (int kt = 0; kt < KTILES; kt++) {
        int kStart = kt * 128;
        load_tile(sm, SM_AH_O, Ah, mBase, validRows, KT, kStart, tid);
        load_tile(sm, SM_AL_O, Al, mBase, validRows, KT, kStart, tid);
        load_tile(sm, SM_BH_O, Bh, nBase, 128, KT, kStart, tid);
        load_tile(sm, SM_BL_O, Bl, nBase, 128, KT, kStart, tid);
        __syncthreads();

#pragma unroll
        for (int k16 = 0; k16 < 8; k16++) {
            uint32_t ah[4][4], al[4][4], bh[4][2], bl[4][2];
#pragma unroll
            for (int mt = 0; mt < 4; mt++) {
                int off = (wm * 64 + mt * 16 + aRow) * LDT + k16 * 16 + aK;
                ldmx4(ah[mt][0], ah[mt][1], ah[mt][2], ah[mt][3],
                      sbase + (SM_AH_O + off) * 2);
                ldmx4(al[mt][0], al[mt][1], al[mt][2], al[mt][3],
                      sbase + (SM_AL_O + off) * 2);
            }
#pragma unroll
            for (int nt = 0; nt < 4; nt++) {
                int off = (wn * 32 + nt * 8 + bRow) * LDT + k16 * 16 + bK;
                ldmx2(bh[nt][0], bh[nt][1], sbase + (SM_BH_O + off) * 2);
                ldmx2(bl[nt][0], bl[nt][1], sbase + (SM_BL_O + off) * 2);
            }
#pragma unroll
            for (int mt = 0; mt < 4; mt++)
#pragma unroll
                for (int nt = 0; nt < 4; nt++) {
                    mma_bf16(d[mt][nt], ah[mt], bh[nt]);
                    mma_bf16(d[mt][nt], ah[mt], bl[nt]);
                    mma_bf16(d[mt][nt], al[mt], bh[nt]);
                }
        }
        __syncthreads();
    }

    // epilogue
#pragma unroll
    for (int mt = 0; mt < 4; mt++) {
        int r0 = mBase + wm * 64 + mt * 16 + (lane >> 2);
#pragma unroll
        for (int nt = 0; nt < 4; nt++) {
            int c0 = nBase + wn * 32 + nt * 8 + (lane & 3) * 2;
#pragma unroll
            for (int half = 0; half < 2; half++) {
                int row = r0 + half * 8;
                if (row >= N_NODES) continue;
                float v0 = d[mt][nt][half * 2 + 0];
                float v1 = d[mt][nt][half * 2 + 1];
                if (SPLIT_OUT) {
                    v0 = fmaxf(v0 + bias[c0], 0.f);
                    v1 = fmaxf(v1 + bias[c0 + 1], 0.f);
                    bf16 h0 = __float2bfloat16(v0);
                    bf16 h1 = __float2bfloat16(v1);
                    bf16 l0 = __float2bfloat16(v0 - __bfloat162float(h0));
                    bf16 l1 = __float2bfloat16(v1 - __bfloat162float(h1));
                    *(uint32_t*)(Ch + (size_t)row * nTotal + c0) =
                        (uint32_t)bf_bits(h0) | ((uint32_t)bf_bits(h1) << 16);
                    *(uint32_t*)(Cl + (size_t)row * nTotal + c0) =
                        (uint32_t)bf_bits(l0) | ((uint32_t)bf_bits(l1) << 16);
                } else {
                    *(float2*)(Cf + (size_t)row * nTotal + c0) =
                        make_float2(v0, v1);
                }
            }
        }
    }
}

// GEMM1: [100000,128] @ W1t^T -> relu(+b1) -> split bf16 g_hh/g_hl (N=256)
__global__ void __launch_bounds__(256) k_gemm1_mma(const float* __restrict__ b1)
{
    mma_gemm_body<1, 1>(g_a1h, g_a1l, g_w1th, g_w1tl, b1,
                        g_hh, g_hl, nullptr, HID_DIM);
}

// GEMM2: [100000,256] @ W2t^T -> fp32 g_h2 (N=128)
__global__ void __launch_bounds__(256) k_gemm2_mma()
{
    mma_gemm_body<2, 0>(g_hh, g_hl, g_w2th, g_w2tl, nullptr,
                        nullptr, nullptr, g_h2, OUT_DIM);
}

// -------------------------------- launcher ---------------------------------

extern "C" void kernel_launch(void* const* d_in, const int* in_sizes, int n_in,
                              void* d_out, int out_size)
{
    const float* x  = (const float*)d_in[0];
    const void*  ei = d_in[1];
    const float* w  = (const float*)d_in[2];
    const float* W1 = (const float*)d_in[3];
    const float* b1 = (const float*)d_in[4];
    const float* W2 = (const float*)d_in[5];
    const float* b2 = (const float*)d_in[6];
    float* out = (float*)d_out;

    const int nodeBlocks = (N_NODES + 255) / 256;
    const int edgeBlocks = (N_EDGES + 255) / 256;
    const int aggBlocks  = (N_NODES * 32 + 255) / 256;
    const int mTiles     = (N_NODES + 127) / 128;          // 782

    cudaFuncSetAttribute(k_gemm1_mma,
        cudaFuncAttributeMaxDynamicSharedMemorySize, SMEM_BYTES);
    cudaFuncSetAttribute(k_gemm2_mma,
        cudaFuncAttributeMaxDynamicSharedMemorySize, SMEM_BYTES);

    k_detect<<<1, 256>>>(ei);
    k_init<<<nodeBlocks, 256>>>();
    k_deg_count<<<edgeBlocks, 256>>>(ei, w);
    k_dis<<<nodeBlocks, 256>>>();
    k_scan<<<1, SCAN_T>>>();
    k_place<<<edgeBlocks, 256>>>(ei, w);

    k_prep_w1<<<(IN_DIM * HID_DIM + 255) / 256, 256>>>(W1);
    k_prep_w2<<<(HID_DIM * OUT_DIM + 255) / 256, 256>>>(W2);

    k_agg_in<<<aggBlocks, 256>>>(x);
    {
        dim3 grid(mTiles, HID_DIM / 128);   // (782, 2)
        k_gemm1_mma<<<grid, 256, SMEM_BYTES>>>(b1);
    }
    {
        dim3 grid(mTiles, OUT_DIM / 128);   // (782, 1)
        k_gemm2_mma<<<grid, 256, SMEM_BYTES>>>();
    }
    k_agg_out<<<aggBlocks, 256>>>(out, b2);
}

// round 11
// speedup vs baseline: 2.0137x; 1.4865x over previous
#include <cuda_runtime.h>
#include <cuda_bf16.h>
#include <cstddef>
#include <cstdint>

// ---------------------------------------------------------------------------
// SpatialGCN: 2-layer GCN, N=100000, E=800000, 128 -> 256 -> 128.
//   layer1: relu( agg(x) @ W1 + b1 )   [aggregate BEFORE GEMM, 128-dim]
//   layer2: agg( h @ W2 ) + b2         [aggregate AFTER GEMM, 128-dim]
// GEMMs: mma.sync m16n8k16 bf16 (base-target PTX) with bf16 hi/lo split
// (AhBh + AhBl + AlBh, fp32 acc). CSR built per launch (parallel scan).
// ---------------------------------------------------------------------------

#define N_NODES 100000
#define N_EDGES 800000
#define IN_DIM 128
#define HID_DIM 256
#define OUT_DIM 128

typedef __nv_bfloat16 bf16;

// -------------------- device scratch (static, no allocs) -------------------
__device__ int   g_is64;
__device__ float g_deg[N_NODES];
__device__ float g_dis[N_NODES];
__device__ int   g_cnt[N_NODES];
__device__ int   g_off[N_NODES + 1];
__device__ int   g_cur[N_NODES];
__device__ int   g_bsum[128];
__device__ int   g_boff[128];
__device__ int   g_csr_src[N_EDGES];
__device__ float g_csr_nrm[N_EDGES];

__device__ bf16  g_a1h[(size_t)N_NODES * IN_DIM];
__device__ bf16  g_a1l[(size_t)N_NODES * IN_DIM];
__device__ bf16  g_hh[(size_t)N_NODES * HID_DIM];
__device__ bf16  g_hl[(size_t)N_NODES * HID_DIM];
__device__ float g_h2[(size_t)N_NODES * OUT_DIM];

__device__ bf16  g_w1th[HID_DIM * IN_DIM];
__device__ bf16  g_w1tl[HID_DIM * IN_DIM];
__device__ bf16  g_w2th[OUT_DIM * HID_DIM];
__device__ bf16  g_w2tl[OUT_DIM * HID_DIM];

// ------------------------------ PTX helpers --------------------------------

__device__ __forceinline__ uint32_t smem_u32(const void* p)
{
    uint32_t a;
    asm("{ .reg .u64 t; cvta.to.shared.u64 t, %1; cvt.u32.u64 %0, t; }"
        : "=r"(a) : "l"(p));
    return a;
}

__device__ __forceinline__ void ldmx4(uint32_t& r0, uint32_t& r1,
                                      uint32_t& r2, uint32_t& r3, uint32_t a)
{
    asm volatile("ldmatrix.sync.aligned.m8n8.x4.shared.b16 {%0,%1,%2,%3}, [%4];"
                 : "=r"(r0), "=r"(r1), "=r"(r2), "=r"(r3) : "r"(a));
}

__device__ __forceinline__ void mma_bf16(float* d, const uint32_t* a,
                                         uint32_t b0, uint32_t b1)
{
    asm volatile(
        "mma.sync.aligned.m16n8k16.row.col.f32.bf16.bf16.f32 "
        "{%0,%1,%2,%3}, {%4,%5,%6,%7}, {%8,%9}, {%0,%1,%2,%3};"
        : "+f"(d[0]), "+f"(d[1]), "+f"(d[2]), "+f"(d[3])
        : "r"(a[0]), "r"(a[1]), "r"(a[2]), "r"(a[3]), "r"(b0), "r"(b1));
}

__device__ __forceinline__ unsigned short bf_bits(bf16 h)
{
    return *(unsigned short*)&h;
}

// ------------------------- edge-index helpers ------------------------------

__device__ __forceinline__ int edge_row(const void* ei, int e, int is64)
{
    if (is64) return (int)((const long long*)ei)[e];
    return ((const int*)ei)[e];
}
__device__ __forceinline__ int edge_col(const void* ei, int e, int is64)
{
    if (is64) return (int)((const long long*)ei)[N_EDGES + e];
    return ((const int*)ei)[N_EDGES + e];
}

// detect dtype (block 0) + zero deg/cnt (all blocks)
__global__ void k_detect_init(const void* ei)
{
    int i = blockIdx.x * blockDim.x + threadIdx.x;
    if (i < N_NODES) { g_deg[i] = 0.f; g_cnt[i] = 0; }
    if (blockIdx.x == 0) {
        const long long* p = (const long long*)ei;
        int t = threadIdx.x;
        int ok = 1;
        for (int k = t; k < 1024; k += blockDim.x) {
            long long a = p[k];
            long long b = p[N_EDGES + k];
            if (a < 0 || a >= N_NODES || b < 0 || b >= N_NODES) ok = 0;
        }
        int all_ok = __syncthreads_and(ok);
        if (t == 0) g_is64 = all_ok;
    }
}

__global__ void k_deg_count(const void* __restrict__ ei,
                            const float* __restrict__ w)
{
    int e = blockIdx.x * blockDim.x + threadIdx.x;
    if (e >= N_EDGES) return;
    int is64 = g_is64;
    int c = edge_col(ei, e, is64);
    atomicAdd(&g_deg[c], w[e]);
    atomicAdd(&g_cnt[c], 1);
}

// ---------------------------- parallel scan ---------------------------------
// pass 1: block sums (coalesced) + dis computation
#define SCAN_BLOCKS ((N_NODES + 1023) / 1024)   // 98
__global__ void __launch_bounds__(1024) k_scan1()
{
    int b = blockIdx.x, t = threadIdx.x;
    int i = b * 1024 + t;
    int v = 0;
    if (i < N_NODES) {
        v = g_cnt[i];
        float d = g_deg[i];
        g_dis[i] = (d > 0.f) ? rsqrtf(d) : 0.f;
    }
    int s = v;
#pragma unroll
    for (int o = 16; o > 0; o >>= 1) s += __shfl_down_sync(0xffffffffu, s, o);
    __shared__ int ws[32];
    if ((t & 31) == 0) ws[t >> 5] = s;
    __syncthreads();
    if (t < 32) {
        int x = ws[t];
#pragma unroll
        for (int o = 16; o > 0; o >>= 1) x += __shfl_down_sync(0xffffffffu, x, o);
        if (t == 0) g_bsum[b] = x;
    }
}

// pass 2: scan 98 partials (1 small block)
__global__ void __launch_bounds__(128) k_scan2()
{
    int t = threadIdx.x;
    __shared__ int s[128];
    int v = (t < SCAN_BLOCKS) ? g_bsum[t] : 0;
    s[t] = v;
    __syncthreads();
#pragma unroll
    for (int o = 1; o < 128; o <<= 1) {
        int x = 0;
        if (t >= o) x = s[t - o];
        __syncthreads();
        s[t] += x;
        __syncthreads();
    }
    if (t < SCAN_BLOCKS) g_boff[t] = s[t] - v;
    if (t == 0) g_off[N_NODES] = N_EDGES;
}

// pass 3: block-local exclusive scan + base, write off/cur
__global__ void __launch_bounds__(1024) k_scan3()
{
    int b = blockIdx.x, t = threadIdx.x;
    int i = b * 1024 + t;
    int v = (i < N_NODES) ? g_cnt[i] : 0;
    int inc = v;
#pragma unroll
    for (int o = 1; o < 32; o <<= 1) {
        int x = __shfl_up_sync(0xffffffffu, inc, o);
        if ((t & 31) >= o) inc += x;
    }
    __shared__ int ws[32], wo[32];
    if ((t & 31) == 31) ws[t >> 5] = inc;
    __syncthreads();
    if (t < 32) {
        int x = ws[t];
        int e = x;
#pragma unroll
        for (int o = 1; o < 32; o <<= 1) {
            int y = __shfl_up_sync(0xffffffffu, e, o);
            if (t >= o) e += y;
        }
        wo[t] = e - x;
    }
    __syncthreads();
    int off = g_boff[b] + wo[t >> 5] + inc - v;
    if (i < N_NODES) { g_off[i] = off; g_cur[i] = off; }
}

__global__ void k_place(const void* __restrict__ ei,
                        const float* __restrict__ w)
{
    int e = blockIdx.x * blockDim.x + threadIdx.x;
    if (e >= N_EDGES) return;
    int is64 = g_is64;
    int r = edge_row(ei, e, is64);
    int c = edge_col(ei, e, is64);
    float nm = g_dis[r] * w[e] * g_dis[c];
    int pos = atomicAdd(&g_cur[c], 1);
    g_csr_src[pos] = r;
    g_csr_nrm[pos] = nm;
}

// ----------------------------- aggregation ---------------------------------

// agg(x) -> bf16 hi/lo split (one warp per node), unroll x2
__global__ void k_agg_in(const float* __restrict__ x)
{
    int gw = (blockIdx.x * blockDim.x + threadIdx.x) >> 5;
    if (gw >= N_NODES) return;
    int lane = threadIdx.x & 31;
    int beg = g_off[gw];
    int end = g_off[gw + 1];
    float4 a0 = make_float4(0.f, 0.f, 0.f, 0.f);
    float4 a1 = make_float4(0.f, 0.f, 0.f, 0.f);
    int e = beg;
    for (; e + 2 <= end; e += 2) {
        int   r0 = g_csr_src[e],     r1 = g_csr_src[e + 1];
        float n0 = g_csr_nrm[e],     n1 = g_csr_nrm[e + 1];
        float4 v0 = *(const float4*)(x + (size_t)r0 * 128 + lane * 4);
        float4 v1 = *(const float4*)(x + (size_t)r1 * 128 + lane * 4);
        a0.x = fmaf(n0, v0.x, a0.x); a0.y = fmaf(n0, v0.y, a0.y);
        a0.z = fmaf(n0, v0.z, a0.z); a0.w = fmaf(n0, v0.w, a0.w);
        a1.x = fmaf(n1, v1.x, a1.x); a1.y = fmaf(n1, v1.y, a1.y);
        a1.z = fmaf(n1, v1.z, a1.z); a1.w = fmaf(n1, v1.w, a1.w);
    }
    if (e < end) {
        int   r0 = g_csr_src[e];
        float n0 = g_csr_nrm[e];
        float4 v0 = *(const float4*)(x + (size_t)r0 * 128 + lane * 4);
        a0.x = fmaf(n0, v0.x, a0.x); a0.y = fmaf(n0, v0.y, a0.y);
        a0.z = fmaf(n0, v0.z, a0.z); a0.w = fmaf(n0, v0.w, a0.w);
    }
    float4 acc = make_float4(a0.x + a1.x, a0.y + a1.y, a0.z + a1.z, a0.w + a1.w);
    bf16 hx = __float2bfloat16(acc.x), hy = __float2bfloat16(acc.y);
    bf16 hz = __float2bfloat16(acc.z), hw = __float2bfloat16(acc.w);
    bf16 lx = __float2bfloat16(acc.x - __bfloat162float(hx));
    bf16 ly = __float2bfloat16(acc.y - __bfloat162float(hy));
    bf16 lz = __float2bfloat16(acc.z - __bfloat162float(hz));
    bf16 lw = __float2bfloat16(acc.w - __bfloat162float(hw));
    size_t o = (size_t)gw * 128 + lane * 4;
    *(ushort4*)(g_a1h + o) = make_ushort4(bf_bits(hx), bf_bits(hy), bf_bits(hz), bf_bits(hw));
    *(ushort4*)(g_a1l + o) = make_ushort4(bf_bits(lx), bf_bits(ly), bf_bits(lz), bf_bits(lw));
}

// agg(g_h2) + b2 -> out (fp32), unroll x2
__global__ void k_agg_out(float* __restrict__ out,
                          const float* __restrict__ b2)
{
    int gw = (blockIdx.x * blockDim.x + threadIdx.x) >> 5;
    if (gw >= N_NODES) return;
    int lane = threadIdx.x & 31;
    int beg = g_off[gw];
    int end = g_off[gw + 1];
    float4 a0 = make_float4(0.f, 0.f, 0.f, 0.f);
    float4 a1 = make_float4(0.f, 0.f, 0.f, 0.f);
    int e = beg;
    for (; e + 2 <= end; e += 2) {
        int   r0 = g_csr_src[e],     r1 = g_csr_src[e + 1];
        float n0 = g_csr_nrm[e],     n1 = g_csr_nrm[e + 1];
        float4 v0 = *(const float4*)(g_h2 + (size_t)r0 * 128 + lane * 4);
        float4 v1 = *(const float4*)(g_h2 + (size_t)r1 * 128 + lane * 4);
        a0.x = fmaf(n0, v0.x, a0.x); a0.y = fmaf(n0, v0.y, a0.y);
        a0.z = fmaf(n0, v0.z, a0.z); a0.w = fmaf(n0, v0.w, a0.w);
        a1.x = fmaf(n1, v1.x, a1.x); a1.y = fmaf(n1, v1.y, a1.y);
        a1.z = fmaf(n1, v1.z, a1.z); a1.w = fmaf(n1, v1.w, a1.w);
    }
    if (e < end) {
        int   r0 = g_csr_src[e];
        float n0 = g_csr_nrm[e];
        float4 v0 = *(const float4*)(g_h2 + (size_t)r0 * 128 + lane * 4);
        a0.x = fmaf(n0, v0.x, a0.x); a0.y = fmaf(n0, v0.y, a0.y);
        a0.z = fmaf(n0, v0.z, a0.z); a0.w = fmaf(n0, v0.w, a0.w);
    }
    float4 bv = *(const float4*)(b2 + lane * 4);
    float4 acc = make_float4(a0.x + a1.x + bv.x, a0.y + a1.y + bv.y,
                             a0.z + a1.z + bv.z, a0.w + a1.w + bv.w);
    *(float4*)(out + (size_t)gw * 128 + lane * 4) = acc;
}

// ---------------------------- weight prep (fused) ---------------------------

__global__ void k_prep(const float* __restrict__ W1,
                       const float* __restrict__ W2)
{
    int i = blockIdx.x * blockDim.x + threadIdx.x;
    if (i < IN_DIM * HID_DIM) {
        int k = i / HID_DIM, n = i % HID_DIM;
        float v = W1[i];
        bf16 hi = __float2bfloat16(v);
        bf16 lo = __float2bfloat16(v - __bfloat162float(hi));
        g_w1th[n * IN_DIM + k] = hi;
        g_w1tl[n * IN_DIM + k] = lo;
    } else {
        int j = i - IN_DIM * HID_DIM;
        if (j >= HID_DIM * OUT_DIM) return;
        int k = j / OUT_DIM, n = j % OUT_DIM;
        float v = W2[j];
        bf16 hi = __float2bfloat16(v);
        bf16 lo = __float2bfloat16(v - __bfloat162float(hi));
        g_w2th[n * HID_DIM + k] = hi;
        g_w2tl[n * HID_DIM + k] = lo;
    }
}

// ------------------------- mma.sync GEMM (bf16 split) -----------------------
// Padded smem rows: 136 bf16 (272B) -> conflict-free ldmatrix.

#define LDT 136

// load ROWS x 128 bf16 tile into padded smem (zero-fill beyond validRows)
template <int ROWS>
__device__ __forceinline__ void load_tile(
    bf16* sm, uint32_t smo, const bf16* __restrict__ g,
    int rowStart, int validRows, int gStride, int kStart, int tid)
{
#pragma unroll
    for (int it = 0; it < ROWS / 16; it++) {
        int c = it * 256 + tid;
        int r  = c >> 4;
        int cc = c & 15;
        uint4 v = make_uint4(0u, 0u, 0u, 0u);
        if (r < validRows)
            v = *(const uint4*)(g + (size_t)(rowStart + r) * gStride + kStart + cc * 8);
        *(uint4*)(sm + smo + r * LDT + cc * 8) = v;
    }
}

// GEMM1: CTA tile 128x256, 8 warps (2m x 4n), warp tile 64x64, K=128 (1 tile).
// smem: AH, AL (128x136), BH, BL (256x136). 208,896 bytes.
#define G1_AH 0
#define G1_AL (128 * LDT)
#define G1_BH (2 * 128 * LDT)
#define G1_BL (2 * 128 * LDT + 256 * LDT)
#define G1_SMEM ((2 * 128 * LDT + 2 * 256 * LDT) * 2)

__global__ void __launch_bounds__(256, 1) k_gemm1_mma(const float* __restrict__ b1)
{
    extern __shared__ bf16 sm[];
    const int tid  = threadIdx.x;
    const int lane = tid & 31;
    const int wid  = tid >> 5;
    const int wm   = wid >> 2;          // 0..1
    const int wn   = wid & 3;           // 0..3
    const int mBase = blockIdx.x * 128;
    const int validRows = min(128, N_NODES - mBase);
    const uint32_t sbase = smem_u32(sm);

    load_tile<128>(sm, G1_AH, g_a1h, mBase, validRows, 128, 0, tid);
    load_tile<128>(sm, G1_AL, g_a1l, mBase, validRows, 128, 0, tid);
    load_tile<256>(sm, G1_BH, g_w1th, 0, 256, 128, 0, tid);
    load_tile<256>(sm, G1_BL, g_w1tl, 0, 256, 128, 0, tid);
    __syncthreads();

    float d[4][8][4];
#pragma unroll
    for (int i = 0; i < 4; i++)
#pragma unroll
        for (int j = 0; j < 8; j++)
#pragma unroll
            for (int r = 0; r < 4; r++) d[i][j][r] = 0.f;

    const int aRow = lane & 15;
    const int aK   = (lane >> 4) << 3;
    const int bRowOff = (lane & 7) + (((lane >> 4) & 1) << 3);
    const int bKOff   = (((lane >> 3) & 1) << 3);

#pragma unroll
    for (int k16 = 0; k16 < 8; k16++) {
        uint32_t ah[4][4], al[4][4];
#pragma unroll
        for (int mt = 0; mt < 4; mt++) {
            int off = (wm * 64 + mt * 16 + aRow) * LDT + k16 * 16 + aK;
            ldmx4(ah[mt][0], ah[mt][1], ah[mt][2], ah[mt][3],
                  sbase + (G1_AH + off) * 2);
            ldmx4(al[mt][0], al[mt][1], al[mt][2], al[mt][3],
                  sbase + (G1_AL + off) * 2);
        }
#pragma unroll
        for (int ntp = 0; ntp < 4; ntp++) {
            int off = (wn * 64 + ntp * 16 + bRowOff) * LDT + k16 * 16 + bKOff;
            uint32_t bh0, bh1, bh2, bh3, bl0, bl1, bl2, bl3;
            ldmx4(bh0, bh1, bh2, bh3, sbase + (G1_BH + off) * 2);
            ldmx4(bl0, bl1, bl2, bl3, sbase + (G1_BL + off) * 2);
#pragma unroll
            for (int mt = 0; mt < 4; mt++) {
                mma_bf16(d[mt][2 * ntp],     ah[mt], bh0, bh1);
                mma_bf16(d[mt][2 * ntp],     ah[mt], bl0, bl1);
                mma_bf16(d[mt][2 * ntp],     al[mt], bh0, bh1);
                mma_bf16(d[mt][2 * ntp + 1], ah[mt], bh2, bh3);
                mma_bf16(d[mt][2 * ntp + 1], ah[mt], bl2, bl3);
                mma_bf16(d[mt][2 * ntp + 1], al[mt], bh2, bh3);
            }
        }
    }

    // epilogue: +b1, relu, hi/lo split -> g_hh / g_hl
#pragma unroll
    for (int mt = 0; mt < 4; mt++) {
        int r0 = mBase + wm * 64 + mt * 16 + (lane >> 2);
#pragma unroll
        for (int nt = 0; nt < 8; nt++) {
            int c0 = wn * 64 + nt * 8 + (lane & 3) * 2;
            float bb0 = b1[c0], bb1 = b1[c0 + 1];
#pragma unroll
            for (int half = 0; half < 2; half++) {
                int row = r0 + half * 8;
                if (row >= N_NODES) continue;
                float v0 = fmaxf(d[mt][nt][half * 2 + 0] + bb0, 0.f);
                float v1 = fmaxf(d[mt][nt][half * 2 + 1] + bb1, 0.f);
                bf16 h0 = __float2bfloat16(v0);
                bf16 h1 = __float2bfloat16(v1);
                bf16 l0 = __float2bfloat16(v0 - __bfloat162float(h0));
                bf16 l1 = __float2bfloat16(v1 - __bfloat162float(h1));
                *(uint32_t*)(g_hh + (size_t)row * HID_DIM + c0) =
                    (uint32_t)bf_bits(h0) | ((uint32_t)bf_bits(h1) << 16);
                *(uint32_t*)(g_hl + (size_t)row * HID_DIM + c0) =
                    (uint32_t)bf_bits(l0) | ((uint32_t)bf_bits(l1) << 16);
            }
        }
    }
}

// GEMM2: CTA tile 128x128, 8 warps (2m x 4n), warp tile 64x32, K=256 (2 tiles).
// smem: AH, AL, BH, BL each 128x136. 139,264 bytes.
#define G2_AH 0
#define G2_AL (128 * LDT)
#define G2_BH (2 * 128 * LDT)
#define G2_BL (3 * 128 * LDT)
#define G2_SMEM ((4 * 128 * LDT) * 2)

__global__ void __launch_bounds__(256, 1) k_gemm2_mma()
{
    extern __shared__ bf16 sm[];
    const int tid  = threadIdx.x;
    const int lane = tid & 31;
    const int wid  = tid >> 5;
    const int wm   = wid >> 2;
    const int wn   = wid & 3;
    const int mBase = blockIdx.x * 128;
    const int validRows = min(128, N_NODES - mBase);
    const uint32_t sbase = smem_u32(sm);

    float d[4][4][4];
#pragma unroll
    for (int i = 0; i < 4; i++)
#pragma unroll
        for (int j = 0; j < 4; j++)
#pragma unroll
            for (int r = 0; r < 4; r++) d[i][j][r] = 0.f;

    const int aRow = lane & 15;
    const int aK   = (lane >> 4) << 3;
    const int bRowOff = (lane & 7) + (((lane >> 4) & 1) << 3);
    const int bKOff   = (((lane >> 3) & 1) << 3);

    for (int kt = 0; kt < 2; kt++) {
        int kStart = kt * 128;
        load_tile<128>(sm, G2_AH, g_hh, mBase, validRows, 256, kStart, tid);
        load_tile<128>(sm, G2_AL, g_hl, mBase, validRows, 256, kStart, tid);
        load_tile<128>(sm, G2_BH, g_w2th, 0, 128, 256, kStart, tid);
        load_tile<128>(sm, G2_BL, g_w2tl, 0, 128, 256, kStart, tid);
        __syncthreads();

#pragma unroll
        for (int k16 = 0; k16 < 8; k16++) {
            uint32_t ah[4][4], al[4][4];
#pragma unroll
            for (int mt = 0; mt < 4; mt++) {
                int off = (wm * 64 + mt * 16 + aRow) * LDT + k16 * 16 + aK;
                ldmx4(ah[mt][0], ah[mt][1], ah[mt][2], ah[mt][3],
                      sbase + (G2_AH + off) * 2);
                ldmx4(al[mt][0], al[mt][1], al[mt][2], al[mt][3],
                      sbase + (G2_AL + off) * 2);
            }
#pragma unroll
            for (int ntp = 0; ntp < 2; ntp++) {
                int off = (wn * 32 + ntp * 16 + bRowOff) * LDT + k16 * 16 + bKOff;
                uint32_t bh0, bh1, bh2, bh3, bl0, bl1, bl2, bl3;
                ldmx4(bh0, bh1, bh2, bh3, sbase + (G2_BH + off) * 2);
                ldmx4(bl0, bl1, bl2, bl3, sbase + (G2_BL + off) * 2);
#pragma unroll
                for (int mt = 0; mt < 4; mt++) {
                    mma_bf16(d[mt][2 * ntp],     ah[mt], bh0, bh1);
                    mma_bf16(d[mt][2 * ntp],     ah[mt], bl0, bl1);
                    mma_bf16(d[mt][2 * ntp],     al[mt], bh0, bh1);
                    mma_bf16(d[mt][2 * ntp + 1], ah[mt], bh2, bh3);
                    mma_bf16(d[mt][2 * ntp + 1], ah[mt], bl2, bl3);
                    mma_bf16(d[mt][2 * ntp + 1], al[mt], bh2, bh3);
                }
            }
        }
        __syncthreads();
    }

    // epilogue: fp32 -> g_h2
#pragma unroll
    for (int mt = 0; mt < 4; mt++) {
        int r0 = mBase + wm * 64 + mt * 16 + (lane >> 2);
#pragma unroll
        for (int nt = 0; nt < 4; nt++) {
            int c0 = wn * 32 + nt * 8 + (lane & 3) * 2;
#pragma unroll
            for (int half = 0; half < 2; half++) {
                int row = r0 + half * 8;
                if (row >= N_NODES) continue;
                *(float2*)(g_h2 + (size_t)row * OUT_DIM + c0) =
                    make_float2(d[mt][nt][half * 2 + 0], d[mt][nt][half * 2 + 1]);
            }
        }
    }
}

// -------------------------------- launcher ---------------------------------

extern "C" void kernel_launch(void* const* d_in, const int* in_sizes, int n_in,
                              void* d_out, int out_size)
{
    const float* x  = (const float*)d_in[0];
    const void*  ei = d_in[1];
    const float* w  = (const float*)d_in[2];
    const float* W1 = (const float*)d_in[3];
    const float* b1 = (const float*)d_in[4];
    const float* W2 = (const float*)d_in[5];
    const float* b2 = (const float*)d_in[6];
    float* out = (float*)d_out;

    const int nodeBlocks = (N_NODES + 255) / 256;
    const int edgeBlocks = (N_EDGES + 255) / 256;
    const int aggBlocks  = (N_NODES * 32 + 255) / 256;
    const int mTiles     = (N_NODES + 127) / 128;          // 782
    const int prepBlocks = (IN_DIM * HID_DIM + HID_DIM * OUT_DIM + 255) / 256;

    cudaFuncSetAttribute(k_gemm1_mma,
        cudaFuncAttributeMaxDynamicSharedMemorySize, G1_SMEM);
    cudaFuncSetAttribute(k_gemm2_mma,
        cudaFuncAttributeMaxDynamicSharedMemorySize, G2_SMEM);

    k_detect_init<<<nodeBlocks, 256>>>(ei);
    k_deg_count<<<edgeBlocks, 256>>>(ei, w);
    k_scan1<<<SCAN_BLOCKS, 1024>>>();
    k_scan2<<<1, 128>>>();
    k_scan3<<<SCAN_BLOCKS, 1024>>>();
    k_place<<<edgeBlocks, 256>>>(ei, w);
    k_prep<<<prepBlocks, 256>>>(W1, W2);

    k_agg_in<<<aggBlocks, 256>>>(x);
    k_gemm1_mma<<<mTiles, 256, G1_SMEM>>>(b1);
    k_gemm2_mma<<<mTiles, 256, G2_SMEM>>>();
    k_agg_out<<<aggBlocks, 256>>>(out, b2);
}

// round 12
// speedup vs baseline: 2.1650x; 1.0751x over previous
#include <cuda_runtime.h>
#include <cuda_bf16.h>
#include <cstddef>
#include <cstdint>

// ---------------------------------------------------------------------------
// SpatialGCN: 2-layer GCN, N=100000, E=800000, 128 -> 256 -> 128.
//   layer1: relu( agg(x) @ W1 + b1 )   [aggregate BEFORE GEMM, 128-dim]
//   layer2: agg( h @ W2 ) + b2         [aggregate AFTER GEMM, 128-dim]
// GEMMs: persistent-CTA mma.sync m16n8k16 bf16 hi/lo split (fp32-accurate),
// weights resident in smem across M-tiles, cp.async tile loads.
// CSR built per launch (parallel scan); edge dtype detected on device.
// ---------------------------------------------------------------------------

#define N_NODES 100000
#define N_EDGES 800000
#define IN_DIM 128
#define HID_DIM 256
#define OUT_DIM 128
#define MTILES ((N_NODES + 127) / 128)     // 782
#define GRID_P 148                          // persistent CTAs (<= SM count)

typedef __nv_bfloat16 bf16;

// -------------------- device scratch (static, no allocs) -------------------
__device__ int   g_is64;
__device__ float g_deg[N_NODES];
__device__ float g_dis[N_NODES];
__device__ int   g_cnt[N_NODES];
__device__ int   g_off[N_NODES + 1];
__device__ int   g_cur[N_NODES];
__device__ int   g_bsum[128];
__device__ int   g_boff[128];
__device__ int   g_csr_src[N_EDGES];
__device__ float g_csr_nrm[N_EDGES];

__device__ bf16  g_a1h[(size_t)N_NODES * IN_DIM];
__device__ bf16  g_a1l[(size_t)N_NODES * IN_DIM];
__device__ bf16  g_hh[(size_t)N_NODES * HID_DIM];
__device__ bf16  g_hl[(size_t)N_NODES * HID_DIM];
__device__ float g_h2[(size_t)N_NODES * OUT_DIM];

__device__ bf16  g_w1th[HID_DIM * IN_DIM];
__device__ bf16  g_w1tl[HID_DIM * IN_DIM];
__device__ bf16  g_w2th[OUT_DIM * HID_DIM];
__device__ bf16  g_w2tl[OUT_DIM * HID_DIM];

// ------------------------------ PTX helpers --------------------------------

__device__ __forceinline__ uint32_t smem_u32(const void* p)
{
    uint32_t a;
    asm("{ .reg .u64 t; cvta.to.shared.u64 t, %1; cvt.u32.u64 %0, t; }"
        : "=r"(a) : "l"(p));
    return a;
}

__device__ __forceinline__ void cp_async16(uint32_t saddr, const void* gptr)
{
    asm volatile("cp.async.cg.shared.global [%0], [%1], 16;"
                 :: "r"(saddr), "l"(__cvta_generic_to_global(gptr)));
}
__device__ __forceinline__ void cp_commit()
{
    asm volatile("cp.async.commit_group;");
}
__device__ __forceinline__ void cp_wait0()
{
    asm volatile("cp.async.wait_group 0;");
}

__device__ __forceinline__ void ldmx4(uint32_t& r0, uint32_t& r1,
                                      uint32_t& r2, uint32_t& r3, uint32_t a)
{
    asm volatile("ldmatrix.sync.aligned.m8n8.x4.shared.b16 {%0,%1,%2,%3}, [%4];"
                 : "=r"(r0), "=r"(r1), "=r"(r2), "=r"(r3) : "r"(a));
}

__device__ __forceinline__ void mma_bf16(float* d, const uint32_t* a,
                                         uint32_t b0, uint32_t b1)
{
    asm volatile(
        "mma.sync.aligned.m16n8k16.row.col.f32.bf16.bf16.f32 "
        "{%0,%1,%2,%3}, {%4,%5,%6,%7}, {%8,%9}, {%0,%1,%2,%3};"
        : "+f"(d[0]), "+f"(d[1]), "+f"(d[2]), "+f"(d[3])
        : "r"(a[0]), "r"(a[1]), "r"(a[2]), "r"(a[3]), "r"(b0), "r"(b1));
}

__device__ __forceinline__ unsigned short bf_bits(bf16 h)
{
    return *(unsigned short*)&h;
}

// ------------------------- edge-index helpers ------------------------------

__device__ __forceinline__ int edge_row(const void* ei, int e, int is64)
{
    if (is64) return (int)((const long long*)ei)[e];
    return ((const int*)ei)[e];
}
__device__ __forceinline__ int edge_col(const void* ei, int e, int is64)
{
    if (is64) return (int)((const long long*)ei)[N_EDGES + e];
    return ((const int*)ei)[N_EDGES + e];
}

__global__ void k_detect_init(const void* ei)
{
    int i = blockIdx.x * blockDim.x + threadIdx.x;
    if (i < N_NODES) { g_deg[i] = 0.f; g_cnt[i] = 0; }
    if (blockIdx.x == 0) {
        const long long* p = (const long long*)ei;
        int t = threadIdx.x;
        int ok = 1;
        for (int k = t; k < 1024; k += blockDim.x) {
            long long a = p[k];
            long long b = p[N_EDGES + k];
            if (a < 0 || a >= N_NODES || b < 0 || b >= N_NODES) ok = 0;
        }
        int all_ok = __syncthreads_and(ok);
        if (t == 0) g_is64 = all_ok;
    }
}

__global__ void k_deg_count(const void* __restrict__ ei,
                            const float* __restrict__ w)
{
    int e = blockIdx.x * blockDim.x + threadIdx.x;
    if (e >= N_EDGES) return;
    int is64 = g_is64;
    int c = edge_col(ei, e, is64);
    atomicAdd(&g_deg[c], w[e]);
    atomicAdd(&g_cnt[c], 1);
}

// ---------------------------- parallel scan ---------------------------------
#define SCAN_BLOCKS ((N_NODES + 1023) / 1024)   // 98
__global__ void __launch_bounds__(1024) k_scan1()
{
    int b = blockIdx.x, t = threadIdx.x;
    int i = b * 1024 + t;
    int v = 0;
    if (i < N_NODES) {
        v = g_cnt[i];
        float d = g_deg[i];
        g_dis[i] = (d > 0.f) ? rsqrtf(d) : 0.f;
    }
    int s = v;
#pragma unroll
    for (int o = 16; o > 0; o >>= 1) s += __shfl_down_sync(0xffffffffu, s, o);
    __shared__ int ws[32];
    if ((t & 31) == 0) ws[t >> 5] = s;
    __syncthreads();
    if (t < 32) {
        int x = ws[t];
#pragma unroll
        for (int o = 16; o > 0; o >>= 1) x += __shfl_down_sync(0xffffffffu, x, o);
        if (t == 0) g_bsum[b] = x;
    }
}

__global__ void __launch_bounds__(128) k_scan2()
{
    int t = threadIdx.x;
    __shared__ int s[128];
    int v = (t < SCAN_BLOCKS) ? g_bsum[t] : 0;
    s[t] = v;
    __syncthreads();
#pragma unroll
    for (int o = 1; o < 128; o <<= 1) {
        int x = 0;
        if (t >= o) x = s[t - o];
        __syncthreads();
        s[t] += x;
        __syncthreads();
    }
    if (t < SCAN_BLOCKS) g_boff[t] = s[t] - v;
    if (t == 0) g_off[N_NODES] = N_EDGES;
}

__global__ void __launch_bounds__(1024) k_scan3()
{
    int b = blockIdx.x, t = threadIdx.x;
    int i = b * 1024 + t;
    int v = (i < N_NODES) ? g_cnt[i] : 0;
    int inc = v;
#pragma unroll
    for (int o = 1; o < 32; o <<= 1) {
        int x = __shfl_up_sync(0xffffffffu, inc, o);
        if ((t & 31) >= o) inc += x;
    }
    __shared__ int ws[32], wo[32];
    if ((t & 31) == 31) ws[t >> 5] = inc;
    __syncthreads();
    if (t < 32) {
        int x = ws[t];
        int e = x;
#pragma unroll
        for (int o = 1; o < 32; o <<= 1) {
            int y = __shfl_up_sync(0xffffffffu, e, o);
            if (t >= o) e += y;
        }
        wo[t] = e - x;
    }
    __syncthreads();
    int off = g_boff[b] + wo[t >> 5] + inc - v;
    if (i < N_NODES) { g_off[i] = off; g_cur[i] = off; }
}

__global__ void k_place(const void* __restrict__ ei,
                        const float* __restrict__ w)
{
    int e = blockIdx.x * blockDim.x + threadIdx.x;
    if (e >= N_EDGES) return;
    int is64 = g_is64;
    int r = edge_row(ei, e, is64);
    int c = edge_col(ei, e, is64);
    float nm = g_dis[r] * w[e] * g_dis[c];
    int pos = atomicAdd(&g_cur[c], 1);
    g_csr_src[pos] = r;
    g_csr_nrm[pos] = nm;
}

// ----------------------------- aggregation ---------------------------------

#define AGG_FMA4(acc, nm, v) \
    do { acc.x = fmaf(nm, v.x, acc.x); acc.y = fmaf(nm, v.y, acc.y); \
         acc.z = fmaf(nm, v.z, acc.z); acc.w = fmaf(nm, v.w, acc.w); } while (0)

__device__ __forceinline__ float4 agg_gather(const float* __restrict__ src,
                                             int beg, int end, int lane)
{
    float4 a0 = make_float4(0.f, 0.f, 0.f, 0.f);
    float4 a1 = make_float4(0.f, 0.f, 0.f, 0.f);
    float4 a2 = make_float4(0.f, 0.f, 0.f, 0.f);
    float4 a3 = make_float4(0.f, 0.f, 0.f, 0.f);
    int e = beg;
    for (; e + 4 <= end; e += 4) {
        int   r0 = g_csr_src[e],     r1 = g_csr_src[e + 1];
        int   r2 = g_csr_src[e + 2], r3 = g_csr_src[e + 3];
        float n0 = g_csr_nrm[e],     n1 = g_csr_nrm[e + 1];
        float n2 = g_csr_nrm[e + 2], n3 = g_csr_nrm[e + 3];
        float4 v0 = *(const float4*)(src + (size_t)r0 * 128 + lane * 4);
        float4 v1 = *(const float4*)(src + (size_t)r1 * 128 + lane * 4);
        float4 v2 = *(const float4*)(src + (size_t)r2 * 128 + lane * 4);
        float4 v3 = *(const float4*)(src + (size_t)r3 * 128 + lane * 4);
        AGG_FMA4(a0, n0, v0); AGG_FMA4(a1, n1, v1);
        AGG_FMA4(a2, n2, v2); AGG_FMA4(a3, n3, v3);
    }
    for (; e < end; e++) {
        int   r0 = g_csr_src[e];
        float n0 = g_csr_nrm[e];
        float4 v0 = *(const float4*)(src + (size_t)r0 * 128 + lane * 4);
        AGG_FMA4(a0, n0, v0);
    }
    return make_float4(a0.x + a1.x + a2.x + a3.x,
                       a0.y + a1.y + a2.y + a3.y,
                       a0.z + a1.z + a2.z + a3.z,
                       a0.w + a1.w + a2.w + a3.w);
}

// agg(x) -> bf16 hi/lo split (one warp per node)
__global__ void k_agg_in(const float* __restrict__ x)
{
    int gw = (blockIdx.x * blockDim.x + threadIdx.x) >> 5;
    if (gw >= N_NODES) return;
    int lane = threadIdx.x & 31;
    float4 acc = agg_gather(x, g_off[gw], g_off[gw + 1], lane);
    bf16 hx = __float2bfloat16(acc.x), hy = __float2bfloat16(acc.y);
    bf16 hz = __float2bfloat16(acc.z), hw = __float2bfloat16(acc.w);
    bf16 lx = __float2bfloat16(acc.x - __bfloat162float(hx));
    bf16 ly = __float2bfloat16(acc.y - __bfloat162float(hy));
    bf16 lz = __float2bfloat16(acc.z - __bfloat162float(hz));
    bf16 lw = __float2bfloat16(acc.w - __bfloat162float(hw));
    size_t o = (size_t)gw * 128 + lane * 4;
    *(ushort4*)(g_a1h + o) = make_ushort4(bf_bits(hx), bf_bits(hy), bf_bits(hz), bf_bits(hw));
    *(ushort4*)(g_a1l + o) = make_ushort4(bf_bits(lx), bf_bits(ly), bf_bits(lz), bf_bits(lw));
}

// agg(g_h2) + b2 -> out (fp32)
__global__ void k_agg_out(float* __restrict__ out,
                          const float* __restrict__ b2)
{
    int gw = (blockIdx.x * blockDim.x + threadIdx.x) >> 5;
    if (gw >= N_NODES) return;
    int lane = threadIdx.x & 31;
    float4 acc = agg_gather(g_h2, g_off[gw], g_off[gw + 1], lane);
    float4 bv = *(const float4*)(b2 + lane * 4);
    acc.x += bv.x; acc.y += bv.y; acc.z += bv.z; acc.w += bv.w;
    *(float4*)(out + (size_t)gw * 128 + lane * 4) = acc;
}

// ---------------------------- weight prep (fused) ---------------------------

__global__ void k_prep(const float* __restrict__ W1,
                       const float* __restrict__ W2)
{
    int i = blockIdx.x * blockDim.x + threadIdx.x;
    if (i < IN_DIM * HID_DIM) {
        int k = i / HID_DIM, n = i % HID_DIM;
        float v = W1[i];
        bf16 hi = __float2bfloat16(v);
        bf16 lo = __float2bfloat16(v - __bfloat162float(hi));
        g_w1th[n * IN_DIM + k] = hi;
        g_w1tl[n * IN_DIM + k] = lo;
    } else {
        int j = i - IN_DIM * HID_DIM;
        if (j >= HID_DIM * OUT_DIM) return;
        int k = j / OUT_DIM, n = j % OUT_DIM;
        float v = W2[j];
        bf16 hi = __float2bfloat16(v);
        bf16 lo = __float2bfloat16(v - __bfloat162float(hi));
        g_w2th[n * HID_DIM + k] = hi;
        g_w2tl[n * HID_DIM + k] = lo;
    }
}

// ------------------------- mma.sync GEMM (bf16 split) -----------------------
// Padded smem rows: 136 bf16 (272B) -> conflict-free ldmatrix.

#define LDT 136
#define TILE_E (128 * LDT)          // elements per 128-row tile buffer

// async load ROWS x 128 bf16 into padded smem (zero-fill beyond validRows)
template <int ROWS>
__device__ __forceinline__ void load_tile_async(
    uint32_t sbase, uint32_t smo /*elements*/, const bf16* __restrict__ g,
    int rowStart, int validRows, int gStride, int kStart, int tid)
{
#pragma unroll
    for (int it = 0; it < ROWS / 16; it++) {
        int c = it * 256 + tid;
        int r  = c >> 4;
        int cc = c & 15;
        uint32_t saddr = sbase + (smo + r * LDT + cc * 8) * 2;
        if (r < validRows) {
            cp_async16(saddr, g + (size_t)(rowStart + r) * gStride + kStart + cc * 8);
        } else {
            *(uint4*)((char*)0 + 0, (uint4*)0);  // placeholder (never taken pattern)
        }
    }
}

// (zero-fill variant used only for the tail tile)
template <int ROWS>
__device__ __forceinline__ void load_tile_async_guard(
    uint32_t sbase, uint32_t smo, bf16* smbase_ptr, const bf16* __restrict__ g,
    int rowStart, int validRows, int gStride, int kStart, int tid)
{
#pragma unroll
    for (int it = 0; it < ROWS / 16; it++) {
        int c = it * 256 + tid;
        int r  = c >> 4;
        int cc = c & 15;
        if (r < validRows) {
            uint32_t saddr = sbase + (smo + r * LDT + cc * 8) * 2;
            cp_async16(saddr, g + (size_t)(rowStart + r) * gStride + kStart + cc * 8);
        } else {
            *(uint4*)(smbase_ptr + smo + r * LDT + cc * 8) =
                make_uint4(0u, 0u, 0u, 0u);
        }
    }
}

// GEMM1 (persistent): CTA tile 128x256, warp tile 64x64, K=128.
// smem: AH, AL (128x136), BH, BL (256x136) = 208,896 bytes.
#define G1_AH 0
#define G1_AL TILE_E
#define G1_BH (2 * TILE_E)
#define G1_BL (2 * TILE_E + 2 * TILE_E)     // B is 256 rows = 2*TILE_E elems
#define G1_SMEM ((2 * TILE_E + 4 * TILE_E) * 2)   // 208896

__global__ void __launch_bounds__(256, 1) k_gemm1_mma(const float* __restrict__ b1)
{
    extern __shared__ bf16 sm[];
    const int tid  = threadIdx.x;
    const int lane = tid & 31;
    const int wid  = tid >> 5;
    const int wm   = wid >> 2;
    const int wn   = wid & 3;
    const uint32_t sbase = smem_u32(sm);

    const int aRow = lane & 15;
    const int aK   = (lane >> 4) << 3;
    const int bRowOff = (lane & 7) + (((lane >> 4) & 1) << 3);
    const int bKOff   = (((lane >> 3) & 1) << 3);

    // resident B (whole W1, hi+lo), loaded once
    load_tile_async_guard<256>(sbase, G1_BH, sm, g_w1th, 0, 256, 128, 0, tid);
    load_tile_async_guard<256>(sbase, G1_BL, sm, g_w1tl, 0, 256, 128, 0, tid);
    cp_commit();

    for (int mt_i = blockIdx.x; mt_i < MTILES; mt_i += GRID_P) {
        const int mBase = mt_i * 128;
        const int validRows = min(128, N_NODES - mBase);
        __syncthreads();   // protect A buffer from previous iteration readers
        load_tile_async_guard<128>(sbase, G1_AH, sm, g_a1h, mBase, validRows, 128, 0, tid);
        load_tile_async_guard<128>(sbase, G1_AL, sm, g_a1l, mBase, validRows, 128, 0, tid);
        cp_commit();
        cp_wait0();
        __syncthreads();

        float d[4][8][4];
#pragma unroll
        for (int i = 0; i < 4; i++)
#pragma unroll
            for (int j = 0; j < 8; j++)
#pragma unroll
                for (int r = 0; r < 4; r++) d[i][j][r] = 0.f;

#pragma unroll
        for (int k16 = 0; k16 < 8; k16++) {
            uint32_t ah[4][4], al[4][4];
#pragma unroll
            for (int mt = 0; mt < 4; mt++) {
                int off = (wm * 64 + mt * 16 + aRow) * LDT + k16 * 16 + aK;
                ldmx4(ah[mt][0], ah[mt][1], ah[mt][2], ah[mt][3],
                      sbase + (G1_AH + off) * 2);
                ldmx4(al[mt][0], al[mt][1], al[mt][2], al[mt][3],
                      sbase + (G1_AL + off) * 2);
            }
#pragma unroll
            for (int ntp = 0; ntp < 4; ntp++) {
                int off = (wn * 64 + ntp * 16 + bRowOff) * LDT + k16 * 16 + bKOff;
                uint32_t bh0, bh1, bh2, bh3, bl0, bl1, bl2, bl3;
                ldmx4(bh0, bh1, bh2, bh3, sbase + (G1_BH + off) * 2);
                ldmx4(bl0, bl1, bl2, bl3, sbase + (G1_BL + off) * 2);
#pragma unroll
                for (int mt = 0; mt < 4; mt++) {
                    mma_bf16(d[mt][2 * ntp],     ah[mt], bh0, bh1);
                    mma_bf16(d[mt][2 * ntp],     ah[mt], bl0, bl1);
                    mma_bf16(d[mt][2 * ntp],     al[mt], bh0, bh1);
                    mma_bf16(d[mt][2 * ntp + 1], ah[mt], bh2, bh3);
                    mma_bf16(d[mt][2 * ntp + 1], ah[mt], bl2, bl3);
                    mma_bf16(d[mt][2 * ntp + 1], al[mt], bh2, bh3);
                }
            }
        }

        // epilogue: +b1, relu, hi/lo split -> g_hh / g_hl
        float bb[8][2];
#pragma unroll
        for (int nt = 0; nt < 8; nt++) {
            int c0 = wn * 64 + nt * 8 + (lane & 3) * 2;
            bb[nt][0] = b1[c0];
            bb[nt][1] = b1[c0 + 1];
        }
#pragma unroll
        for (int mt = 0; mt < 4; mt++) {
            int r0 = mBase + wm * 64 + mt * 16 + (lane >> 2);
#pragma unroll
            for (int nt = 0; nt < 8; nt++) {
                int c0 = wn * 64 + nt * 8 + (lane & 3) * 2;
#pragma unroll
                for (int half = 0; half < 2; half++) {
                    int row = r0 + half * 8;
                    if (row >= N_NODES) continue;
                    float v0 = fmaxf(d[mt][nt][half * 2 + 0] + bb[nt][0], 0.f);
                    float v1 = fmaxf(d[mt][nt][half * 2 + 1] + bb[nt][1], 0.f);
                    bf16 h0 = __float2bfloat16(v0);
                    bf16 h1 = __float2bfloat16(v1);
                    bf16 l0 = __float2bfloat16(v0 - __bfloat162float(h0));
                    bf16 l1 = __float2bfloat16(v1 - __bfloat162float(h1));
                    *(uint32_t*)(g_hh + (size_t)row * HID_DIM + c0) =
                        (uint32_t)bf_bits(h0) | ((uint32_t)bf_bits(h1) << 16);
                    *(uint32_t*)(g_hl + (size_t)row * HID_DIM + c0) =
                        (uint32_t)bf_bits(l0) | ((uint32_t)bf_bits(l1) << 16);
                }
            }
        }
    }
}

// GEMM2 (persistent): CTA tile 128x128, warp tile 64x32, K=256 (2 resident
// B tiles). smem: B0H,B0L,B1H,B1L + AH,AL each 128x136 = 208,896 bytes.
#define G2_B0H 0
#define G2_B0L TILE_E
#define G2_B1H (2 * TILE_E)
#define G2_B1L (3 * TILE_E)
#define G2_AH  (4 * TILE_E)
#define G2_AL  (5 * TILE_E)
#define G2_SMEM (6 * TILE_E * 2)            // 208896

__global__ void __launch_bounds__(256, 1) k_gemm2_mma()
{
    extern __shared__ bf16 sm[];
    const int tid  = threadIdx.x;
    const int lane = tid & 31;
    const int wid  = tid >> 5;
    const int wm   = wid >> 2;
    const int wn   = wid & 3;
    const uint32_t sbase = smem_u32(sm);

    const int aRow = lane & 15;
    const int aK   = (lane >> 4) << 3;
    const int bRowOff = (lane & 7) + (((lane >> 4) & 1) << 3);
    const int bKOff   = (((lane >> 3) & 1) << 3);

    // resident B: both K-tiles of W2t (hi+lo), loaded once
    load_tile_async_guard<128>(sbase, G2_B0H, sm, g_w2th, 0, 128, 256, 0, tid);
    load_tile_async_guard<128>(sbase, G2_B0L, sm, g_w2tl, 0, 128, 256, 0, tid);
    load_tile_async_guard<128>(sbase, G2_B1H, sm, g_w2th, 0, 128, 256, 128, tid);
    load_tile_async_guard<128>(sbase, G2_B1L, sm, g_w2tl, 0, 128, 256, 128, tid);
    cp_commit();

    for (int mt_i = blockIdx.x; mt_i < MTILES; mt_i += GRID_P) {
        const int mBase = mt_i * 128;
        const int validRows = min(128, N_NODES - mBase);

        float d[4][4][4];
#pragma unroll
        for (int i = 0; i < 4; i++)
#pragma unroll
            for (int j = 0; j < 4; j++)
#pragma unroll
                for (int r = 0; r < 4; r++) d[i][j][r] = 0.f;

#pragma unroll
        for (int kt = 0; kt < 2; kt++) {
            const uint32_t BH = kt ? G2_B1H : G2_B0H;
            const uint32_t BL = kt ? G2_B1L : G2_B0L;
            __syncthreads();   // protect A buffer
            load_tile_async_guard<128>(sbase, G2_AH, sm, g_hh, mBase, validRows,
                                       256, kt * 128, tid);
            load_tile_async_guard<128>(sbase, G2_AL, sm, g_hl, mBase, validRows,
                                       256, kt * 128, tid);
            cp_commit();
            cp_wait0();
            __syncthreads();

#pragma unroll
            for (int k16 = 0; k16 < 8; k16++) {
                uint32_t ah[4][4], al[4][4];
#pragma unroll
                for (int mt = 0; mt < 4; mt++) {
                    int off = (wm * 64 + mt * 16 + aRow) * LDT + k16 * 16 + aK;
                    ldmx4(ah[mt][0], ah[mt][1], ah[mt][2], ah[mt][3],
                          sbase + (G2_AH + off) * 2);
                    ldmx4(al[mt][0], al[mt][1], al[mt][2], al[mt][3],
                          sbase + (G2_AL + off) * 2);
                }
#pragma unroll
                for (int ntp = 0; ntp < 2; ntp++) {
                    int off = (wn * 32 + ntp * 16 + bRowOff) * LDT + k16 * 16 + bKOff;
                    uint32_t bh0, bh1, bh2, bh3, bl0, bl1, bl2, bl3;
                    ldmx4(bh0, bh1, bh2, bh3, sbase + (BH + off) * 2);
                    ldmx4(bl0, bl1, bl2, bl3, sbase + (BL + off) * 2);
#pragma unroll
                    for (int mt = 0; mt < 4; mt++) {
                        mma_bf16(d[mt][2 * ntp],     ah[mt], bh0, bh1);
                        mma_bf16(d[mt][2 * ntp],     ah[mt], bl0, bl1);
                        mma_bf16(d[mt][2 * ntp],     al[mt], bh0, bh1);
                        mma_bf16(d[mt][2 * ntp + 1], ah[mt], bh2, bh3);
                        mma_bf16(d[mt][2 * ntp + 1], ah[mt], bl2, bl3);
                        mma_bf16(d[mt][2 * ntp + 1], al[mt], bh2, bh3);
                    }
                }
            }
        }

        // epilogue: fp32 -> g_h2
#pragma unroll
        for (int mt = 0; mt < 4; mt++) {
            int r0 = mBase + wm * 64 + mt * 16 + (lane >> 2);
#pragma unroll
            for (int nt = 0; nt < 4; nt++) {
                int c0 = wn * 32 + nt * 8 + (lane & 3) * 2;
#pragma unroll
                for (int half = 0; half < 2; half++) {
                    int row = r0 + half * 8;
                    if (row >= N_NODES) continue;
                    *(float2*)(g_h2 + (size_t)row * OUT_DIM + c0) =
                        make_float2(d[mt][nt][half * 2 + 0],
                                    d[mt][nt][half * 2 + 1]);
                }
            }
        }
    }
}

// -------------------------------- launcher ---------------------------------

extern "C" void kernel_launch(void* const* d_in, const int* in_sizes, int n_in,
                              void* d_out, int out_size)
{
    const float* x  = (const float*)d_in[0];
    const void*  ei = d_in[1];
    const float* w  = (const float*)d_in[2];
    const float* W1 = (const float*)d_in[3];
    const float* b1 = (const float*)d_in[4];
    const float* W2 = (const float*)d_in[5];
    const float* b2 = (const float*)d_in[6];
    float* out = (float*)d_out;

    const int nodeBlocks = (N_NODES + 255) / 256;
    const int edgeBlocks = (N_EDGES + 255) / 256;
    const int aggBlocks  = (N_NODES * 32 + 255) / 256;
    const int prepBlocks = (IN_DIM * HID_DIM + HID_DIM * OUT_DIM + 255) / 256;

    cudaFuncSetAttribute(k_gemm1_mma,
        cudaFuncAttributeMaxDynamicSharedMemorySize, G1_SMEM);
    cudaFuncSetAttribute(k_gemm2_mma,
        cudaFuncAttributeMaxDynamicSharedMemorySize, G2_SMEM);

    k_detect_init<<<nodeBlocks, 256>>>(ei);
    k_deg_count<<<edgeBlocks, 256>>>(ei, w);
    k_scan1<<<SCAN_BLOCKS, 1024>>>();
    k_scan2<<<1, 128>>>();
    k_scan3<<<SCAN_BLOCKS, 1024>>>();
    k_place<<<edgeBlocks, 256>>>(ei, w);
    k_prep<<<prepBlocks, 256>>>(W1, W2);

    k_agg_in<<<aggBlocks, 256>>>(x);
    k_gemm1_mma<<<GRID_P, 256, G1_SMEM>>>(b1);
    k_gemm2_mma<<<GRID_P, 256, G2_SMEM>>>();
    k_agg_out<<<aggBlocks, 256>>>(out, b2);
}

// round 13
// speedup vs baseline: 2.2249x; 1.0277x over previous
#include <cuda_runtime.h>
#include <cuda_bf16.h>
#include <cstddef>
#include <cstdint>

// ---------------------------------------------------------------------------
// SpatialGCN: 2-layer GCN, N=100000, E=800000, 128 -> 256 -> 128.
//   layer1: relu( agg(x) @ W1 + b1 )   [aggregate BEFORE GEMM, 128-dim]
//   layer2: agg( h @ W2 ) + b2         [aggregate AFTER GEMM, 128-dim]
// GEMMs: persistent-CTA mma.sync m16n8k16 bf16 hi/lo split (fp32-accurate),
// weights resident in smem, cp.async tile loads.
// 7-launch pipeline; deg/cnt zeroed at END of each run (globals start zero).
// ---------------------------------------------------------------------------

#define N_NODES 100000
#define N_EDGES 800000
#define IN_DIM 128
#define HID_DIM 256
#define OUT_DIM 128
#define MTILES ((N_NODES + 127) / 128)     // 782
#define GRID_P 148

typedef __nv_bfloat16 bf16;

#define EDGE_BLOCKS ((N_EDGES + 255) / 256)            // 3125
#define PREP_ELEMS (IN_DIM * HID_DIM + HID_DIM * OUT_DIM)  // 65536
#define PREP_BLOCKS ((PREP_ELEMS + 255) / 256)         // 256

// -------------------- device scratch (static, no allocs) -------------------
__device__ float g_deg[N_NODES];           // MUST be zero at kernel_launch entry
__device__ int   g_cnt[N_NODES];           // (zero-init at load; re-zeroed at end)
__device__ float g_dis[N_NODES];
__device__ int   g_off[N_NODES + 1];
__device__ int   g_cur[N_NODES];
__device__ int   g_csr_src[N_EDGES];
__device__ float g_csr_nrm[N_EDGES];

__device__ bf16  g_a1h[(size_t)N_NODES * IN_DIM];
__device__ bf16  g_a1l[(size_t)N_NODES * IN_DIM];
__device__ bf16  g_hh[(size_t)N_NODES * HID_DIM];
__device__ bf16  g_hl[(size_t)N_NODES * HID_DIM];
__device__ float g_h2[(size_t)N_NODES * OUT_DIM];

__device__ bf16  g_w1th[HID_DIM * IN_DIM];
__device__ bf16  g_w1tl[HID_DIM * IN_DIM];
__device__ bf16  g_w2th[OUT_DIM * HID_DIM];
__device__ bf16  g_w2tl[OUT_DIM * HID_DIM];

// ------------------------------ PTX helpers --------------------------------

__device__ __forceinline__ uint32_t smem_u32(const void* p)
{
    uint32_t a;
    asm("{ .reg .u64 t; cvta.to.shared.u64 t, %1; cvt.u32.u64 %0, t; }"
        : "=r"(a) : "l"(p));
    return a;
}

__device__ __forceinline__ void cp_async16(uint32_t saddr, const void* gptr)
{
    asm volatile("cp.async.cg.shared.global [%0], [%1], 16;"
                 :: "r"(saddr), "l"(__cvta_generic_to_global(gptr)));
}
__device__ __forceinline__ void cp_commit()
{
    asm volatile("cp.async.commit_group;");
}
__device__ __forceinline__ void cp_wait0()
{
    asm volatile("cp.async.wait_group 0;");
}

__device__ __forceinline__ void ldmx4(uint32_t& r0, uint32_t& r1,
                                      uint32_t& r2, uint32_t& r3, uint32_t a)
{
    asm volatile("ldmatrix.sync.aligned.m8n8.x4.shared.b16 {%0,%1,%2,%3}, [%4];"
                 : "=r"(r0), "=r"(r1), "=r"(r2), "=r"(r3) : "r"(a));
}

__device__ __forceinline__ void mma_bf16(float* d, const uint32_t* a,
                                         uint32_t b0, uint32_t b1)
{
    asm volatile(
        "mma.sync.aligned.m16n8k16.row.col.f32.bf16.bf16.f32 "
        "{%0,%1,%2,%3}, {%4,%5,%6,%7}, {%8,%9}, {%0,%1,%2,%3};"
        : "+f"(d[0]), "+f"(d[1]), "+f"(d[2]), "+f"(d[3])
        : "r"(a[0]), "r"(a[1]), "r"(a[2]), "r"(a[3]), "r"(b0), "r"(b1));
}

__device__ __forceinline__ unsigned short bf_bits(bf16 h)
{
    return *(unsigned short*)&h;
}

// --------------------- per-block edge-dtype detection ----------------------
// Reads first 16 int64-interpreted entries of each half; for int32 data the
// high words are random node indices (nonzero w.p. ~1-1e-5 each) so the
// probability of a false int64 verdict is ~0. Uniform per block.

__device__ __forceinline__ int detect_is64_block(const void* ei)
{
    __shared__ int s_is64;
    int t = threadIdx.x;
    int ok = 1;
    if (t < 16) {
        const long long* p = (const long long*)ei;
        long long a = p[t];
        long long b = p[N_EDGES + t];
        if (a < 0 || a >= N_NODES || b < 0 || b >= N_NODES) ok = 0;
    }
    unsigned bad = __ballot_sync(0xffffffffu, ok == 0);
    if (t == 0) s_is64 = (bad == 0u);
    __syncthreads();
    return s_is64;
}

__device__ __forceinline__ int edge_row(const void* ei, int e, int is64)
{
    if (is64) return (int)((const long long*)ei)[e];
    return ((const int*)ei)[e];
}
__device__ __forceinline__ int edge_col(const void* ei, int e, int is64)
{
    if (is64) return (int)((const long long*)ei)[N_EDGES + e];
    return ((const int*)ei)[N_EDGES + e];
}

// ---------------- launch 1: deg/cnt accumulation + weight prep -------------

__global__ void k_deg_prep(const void* __restrict__ ei,
                           const float* __restrict__ w,
                           const float* __restrict__ W1,
                           const float* __restrict__ W2)
{
    if (blockIdx.x < EDGE_BLOCKS) {
        int is64 = detect_is64_block(ei);
        int e = blockIdx.x * blockDim.x + threadIdx.x;
        if (e >= N_EDGES) return;
        int c = edge_col(ei, e, is64);
        atomicAdd(&g_deg[c], w[e]);
        atomicAdd(&g_cnt[c], 1);
    } else {
        int i = (blockIdx.x - EDGE_BLOCKS) * blockDim.x + threadIdx.x;
        if (i < IN_DIM * HID_DIM) {
            int k = i / HID_DIM, n = i % HID_DIM;
            float v = W1[i];
            bf16 hi = __float2bfloat16(v);
            bf16 lo = __float2bfloat16(v - __bfloat162float(hi));
            g_w1th[n * IN_DIM + k] = hi;
            g_w1tl[n * IN_DIM + k] = lo;
        } else {
            int j = i - IN_DIM * HID_DIM;
            if (j >= HID_DIM * OUT_DIM) return;
            int k = j / OUT_DIM, n = j % OUT_DIM;
            float v = W2[j];
            bf16 hi = __float2bfloat16(v);
            bf16 lo = __float2bfloat16(v - __bfloat162float(hi));
            g_w2th[n * HID_DIM + k] = hi;
            g_w2tl[n * HID_DIM + k] = lo;
        }
    }
}

// -------------- launch 2: fused scan (brute block prefix) + dis ------------
#define SCAN_BLOCKS ((N_NODES + 1023) / 1024)   // 98

__global__ void __launch_bounds__(1024) k_scan_fused()
{
    int b = blockIdx.x, t = threadIdx.x;
    int i = b * 1024 + t;

    // base = sum of cnt[0 .. b*1024) (int4, coalesced; <=24 iters/thread)
    int partial = 0;
    {
        const int4* c4 = (const int4*)g_cnt;
        int lim = (b * 1024) >> 2;
        for (int j = t; j < lim; j += 1024) {
            int4 q = c4[j];
            partial += q.x + q.y + q.z + q.w;
        }
    }
#pragma unroll
    for (int o = 16; o > 0; o >>= 1)
        partial += __shfl_down_sync(0xffffffffu, partial, o);
    __shared__ int ws[32];
    __shared__ int s_base;
    if ((t & 31) == 0) ws[t >> 5] = partial;
    __syncthreads();
    if (t < 32) {
        int x = ws[t];
#pragma unroll
        for (int o = 16; o > 0; o >>= 1)
            x += __shfl_down_sync(0xffffffffu, x, o);
        if (t == 0) s_base = x;
    }

    // dis + local value
    int v = 0;
    if (i < N_NODES) {
        v = g_cnt[i];
        float d = g_deg[i];
        g_dis[i] = (d > 0.f) ? rsqrtf(d) : 0.f;
    }

    // block-local exclusive scan
    int inc = v;
#pragma unroll
    for (int o = 1; o < 32; o <<= 1) {
        int x = __shfl_up_sync(0xffffffffu, inc, o);
        if ((t & 31) >= o) inc += x;
    }
    __shared__ int ws2[32], wo[32];
    if ((t & 31) == 31) ws2[t >> 5] = inc;
    __syncthreads();     // s_base + ws2 ready
    if (t < 32) {
        int x = ws2[t];
        int e = x;
#pragma unroll
        for (int o = 1; o < 32; o <<= 1) {
            int y = __shfl_up_sync(0xffffffffu, e, o);
            if (t >= o) e += y;
        }
        wo[t] = e - x;
    }
    __syncthreads();
    int off = s_base + wo[t >> 5] + inc - v;
    if (i < N_NODES) { g_off[i] = off; g_cur[i] = off; }
    if (b == 0 && t == 0) g_off[N_NODES] = N_EDGES;
}

// --------------------------- launch 3: CSR place ----------------------------

__global__ void k_place(const void* __restrict__ ei,
                        const float* __restrict__ w)
{
    int is64 = detect_is64_block(ei);
    int e = blockIdx.x * blockDim.x + threadIdx.x;
    if (e >= N_EDGES) return;
    int r = edge_row(ei, e, is64);
    int c = edge_col(ei, e, is64);
    float nm = g_dis[r] * w[e] * g_dis[c];
    int pos = atomicAdd(&g_cur[c], 1);
    g_csr_src[pos] = r;
    g_csr_nrm[pos] = nm;
}

// ----------------------------- aggregation ---------------------------------

#define AGG_FMA4(acc, nm, v) \
    do { acc.x = fmaf(nm, v.x, acc.x); acc.y = fmaf(nm, v.y, acc.y); \
         acc.z = fmaf(nm, v.z, acc.z); acc.w = fmaf(nm, v.w, acc.w); } while (0)

__device__ __forceinline__ float4 agg_gather(const float* __restrict__ src,
                                             int beg, int end, int lane)
{
    float4 a0 = make_float4(0.f, 0.f, 0.f, 0.f);
    float4 a1 = make_float4(0.f, 0.f, 0.f, 0.f);
    float4 a2 = make_float4(0.f, 0.f, 0.f, 0.f);
    float4 a3 = make_float4(0.f, 0.f, 0.f, 0.f);
    int e = beg;
    for (; e + 4 <= end; e += 4) {
        int   r0 = g_csr_src[e],     r1 = g_csr_src[e + 1];
        int   r2 = g_csr_src[e + 2], r3 = g_csr_src[e + 3];
        float n0 = g_csr_nrm[e],     n1 = g_csr_nrm[e + 1];
        float n2 = g_csr_nrm[e + 2], n3 = g_csr_nrm[e + 3];
        float4 v0 = __ldg((const float4*)(src + (size_t)r0 * 128 + lane * 4));
        float4 v1 = __ldg((const float4*)(src + (size_t)r1 * 128 + lane * 4));
        float4 v2 = __ldg((const float4*)(src + (size_t)r2 * 128 + lane * 4));
        float4 v3 = __ldg((const float4*)(src + (size_t)r3 * 128 + lane * 4));
        AGG_FMA4(a0, n0, v0); AGG_FMA4(a1, n1, v1);
        AGG_FMA4(a2, n2, v2); AGG_FMA4(a3, n3, v3);
    }
    for (; e < end; e++) {
        int   r0 = g_csr_src[e];
        float n0 = g_csr_nrm[e];
        float4 v0 = __ldg((const float4*)(src + (size_t)r0 * 128 + lane * 4));
        AGG_FMA4(a0, n0, v0);
    }
    return make_float4(a0.x + a1.x + a2.x + a3.x,
                       a0.y + a1.y + a2.y + a3.y,
                       a0.z + a1.z + a2.z + a3.z,
                       a0.w + a1.w + a2.w + a3.w);
}

// launch 4 (PROFILED SLOT): agg(x) -> bf16 hi/lo split (one warp per node)
__global__ void k_agg_in(const float* __restrict__ x)
{
    int gw = (blockIdx.x * blockDim.x + threadIdx.x) >> 5;
    if (gw >= N_NODES) return;
    int lane = threadIdx.x & 31;
    float4 acc = agg_gather(x, g_off[gw], g_off[gw + 1], lane);
    bf16 hx = __float2bfloat16(acc.x), hy = __float2bfloat16(acc.y);
    bf16 hz = __float2bfloat16(acc.z), hw = __float2bfloat16(acc.w);
    bf16 lx = __float2bfloat16(acc.x - __bfloat162float(hx));
    bf16 ly = __float2bfloat16(acc.y - __bfloat162float(hy));
    bf16 lz = __float2bfloat16(acc.z - __bfloat162float(hz));
    bf16 lw = __float2bfloat16(acc.w - __bfloat162float(hw));
    size_t o = (size_t)gw * 128 + lane * 4;
    *(ushort4*)(g_a1h + o) = make_ushort4(bf_bits(hx), bf_bits(hy), bf_bits(hz), bf_bits(hw));
    *(ushort4*)(g_a1l + o) = make_ushort4(bf_bits(lx), bf_bits(ly), bf_bits(lz), bf_bits(lw));
}

// launch 7: agg(g_h2) + b2 -> out ; also re-zero g_deg/g_cnt for next run
__global__ void k_agg_out(float* __restrict__ out,
                          const float* __restrict__ b2)
{
    int gt = blockIdx.x * blockDim.x + threadIdx.x;
    if (gt < N_NODES) { g_deg[gt] = 0.f; g_cnt[gt] = 0; }
    int gw = gt >> 5;
    if (gw >= N_NODES) return;
    int lane = threadIdx.x & 31;
    float4 acc = agg_gather(g_h2, g_off[gw], g_off[gw + 1], lane);
    float4 bv = *(const float4*)(b2 + lane * 4);
    acc.x += bv.x; acc.y += bv.y; acc.z += bv.z; acc.w += bv.w;
    *(float4*)(out + (size_t)gw * 128 + lane * 4) = acc;
}

// ------------------------- mma.sync GEMM (bf16 split) -----------------------

#define LDT 136
#define TILE_E (128 * LDT)

template <int ROWS>
__device__ __forceinline__ void load_tile_async_guard(
    uint32_t sbase, uint32_t smo, bf16* smbase_ptr, const bf16* __restrict__ g,
    int rowStart, int validRows, int gStride, int kStart, int tid)
{
#pragma unroll
    for (int it = 0; it < ROWS / 16; it++) {
        int c = it * 256 + tid;
        int r  = c >> 4;
        int cc = c & 15;
        if (r < validRows) {
            uint32_t saddr = sbase + (smo + r * LDT + cc * 8) * 2;
            cp_async16(saddr, g + (size_t)(rowStart + r) * gStride + kStart + cc * 8);
        } else {
            *(uint4*)(smbase_ptr + smo + r * LDT + cc * 8) =
                make_uint4(0u, 0u, 0u, 0u);
        }
    }
}

// GEMM1 (persistent): CTA tile 128x256, warp tile 64x64, K=128.
#define G1_AH 0
#define G1_AL TILE_E
#define G1_BH (2 * TILE_E)
#define G1_BL (4 * TILE_E)
#define G1_SMEM (6 * TILE_E * 2)   // 208896

__global__ void __launch_bounds__(256, 1) k_gemm1_mma(const float* __restrict__ b1)
{
    extern __shared__ bf16 sm[];
    const int tid  = threadIdx.x;
    const int lane = tid & 31;
    const int wid  = tid >> 5;
    const int wm   = wid >> 2;
    const int wn   = wid & 3;
    const uint32_t sbase = smem_u32(sm);

    const int aRow = lane & 15;
    const int aK   = (lane >> 4) << 3;
    const int bRowOff = (lane & 7) + (((lane >> 4) & 1) << 3);
    const int bKOff   = (((lane >> 3) & 1) << 3);

    load_tile_async_guard<256>(sbase, G1_BH, sm, g_w1th, 0, 256, 128, 0, tid);
    load_tile_async_guard<256>(sbase, G1_BL, sm, g_w1tl, 0, 256, 128, 0, tid);
    cp_commit();

    for (int mt_i = blockIdx.x; mt_i < MTILES; mt_i += GRID_P) {
        const int mBase = mt_i * 128;
        const int validRows = min(128, N_NODES - mBase);
        __syncthreads();
        load_tile_async_guard<128>(sbase, G1_AH, sm, g_a1h, mBase, validRows, 128, 0, tid);
        load_tile_async_guard<128>(sbase, G1_AL, sm, g_a1l, mBase, validRows, 128, 0, tid);
        cp_commit();
        cp_wait0();
        __syncthreads();

        float d[4][8][4];
#pragma unroll
        for (int i = 0; i < 4; i++)
#pragma unroll
            for (int j = 0; j < 8; j++)
#pragma unroll
                for (int r = 0; r < 4; r++) d[i][j][r] = 0.f;

#pragma unroll
        for (int k16 = 0; k16 < 8; k16++) {
            uint32_t ah[4][4], al[4][4];
#pragma unroll
            for (int mt = 0; mt < 4; mt++) {
                int off = (wm * 64 + mt * 16 + aRow) * LDT + k16 * 16 + aK;
                ldmx4(ah[mt][0], ah[mt][1], ah[mt][2], ah[mt][3],
                      sbase + (G1_AH + off) * 2);
                ldmx4(al[mt][0], al[mt][1], al[mt][2], al[mt][3],
                      sbase + (G1_AL + off) * 2);
            }
#pragma unroll
            for (int ntp = 0; ntp < 4; ntp++) {
                int off = (wn * 64 + ntp * 16 + bRowOff) * LDT + k16 * 16 + bKOff;
                uint32_t bh0, bh1, bh2, bh3, bl0, bl1, bl2, bl3;
                ldmx4(bh0, bh1, bh2, bh3, sbase + (G1_BH + off) * 2);
                ldmx4(bl0, bl1, bl2, bl3, sbase + (G1_BL + off) * 2);
#pragma unroll
                for (int mt = 0; mt < 4; mt++) {
                    mma_bf16(d[mt][2 * ntp],     ah[mt], bh0, bh1);
                    mma_bf16(d[mt][2 * ntp],     ah[mt], bl0, bl1);
                    mma_bf16(d[mt][2 * ntp],     al[mt], bh0, bh1);
                    mma_bf16(d[mt][2 * ntp + 1], ah[mt], bh2, bh3);
                    mma_bf16(d[mt][2 * ntp + 1], ah[mt], bl2, bl3);
                    mma_bf16(d[mt][2 * ntp + 1], al[mt], bh2, bh3);
                }
            }
        }

        float bb[8][2];
#pragma unroll
        for (int nt = 0; nt < 8; nt++) {
            int c0 = wn * 64 + nt * 8 + (lane & 3) * 2;
            bb[nt][0] = b1[c0];
            bb[nt][1] = b1[c0 + 1];
        }
#pragma unroll
        for (int mt = 0; mt < 4; mt++) {
            int r0 = mBase + wm * 64 + mt * 16 + (lane >> 2);
#pragma unroll
            for (int nt = 0; nt < 8; nt++) {
                int c0 = wn * 64 + nt * 8 + (lane & 3) * 2;
#pragma unroll
                for (int half = 0; half < 2; half++) {
                    int row = r0 + half * 8;
                    if (row >= N_NODES) continue;
                    float v0 = fmaxf(d[mt][nt][half * 2 + 0] + bb[nt][0], 0.f);
                    float v1 = fmaxf(d[mt][nt][half * 2 + 1] + bb[nt][1], 0.f);
                    bf16 h0 = __float2bfloat16(v0);
                    bf16 h1 = __float2bfloat16(v1);
                    bf16 l0 = __float2bfloat16(v0 - __bfloat162float(h0));
                    bf16 l1 = __float2bfloat16(v1 - __bfloat162float(h1));
                    *(uint32_t*)(g_hh + (size_t)row * HID_DIM + c0) =
                        (uint32_t)bf_bits(h0) | ((uint32_t)bf_bits(h1) << 16);
                    *(uint32_t*)(g_hl + (size_t)row * HID_DIM + c0) =
                        (uint32_t)bf_bits(l0) | ((uint32_t)bf_bits(l1) << 16);
                }
            }
        }
    }
}

// GEMM2 (persistent): CTA tile 128x128, warp tile 64x32, K=256.
#define G2_B0H 0
#define G2_B0L TILE_E
#define G2_B1H (2 * TILE_E)
#define G2_B1L (3 * TILE_E)
#define G2_AH  (4 * TILE_E)
#define G2_AL  (5 * TILE_E)
#define G2_SMEM (6 * TILE_E * 2)            // 208896

__global__ void __launch_bounds__(256, 1) k_gemm2_mma()
{
    extern __shared__ bf16 sm[];
    const int tid  = threadIdx.x;
    const int lane = tid & 31;
    const int wid  = tid >> 5;
    const int wm   = wid >> 2;
    const int wn   = wid & 3;
    const uint32_t sbase = smem_u32(sm);

    const int aRow = lane & 15;
    const int aK   = (lane >> 4) << 3;
    const int bRowOff = (lane & 7) + (((lane >> 4) & 1) << 3);
    const int bKOff   = (((lane >> 3) & 1) << 3);

    load_tile_async_guard<128>(sbase, G2_B0H, sm, g_w2th, 0, 128, 256, 0, tid);
    load_tile_async_guard<128>(sbase, G2_B0L, sm, g_w2tl, 0, 128, 256, 0, tid);
    load_tile_async_guard<128>(sbase, G2_B1H, sm, g_w2th, 0, 128, 256, 128, tid);
    load_tile_async_guard<128>(sbase, G2_B1L, sm, g_w2tl, 0, 128, 256, 128, tid);
    cp_commit();

    for (int mt_i = blockIdx.x; mt_i < MTILES; mt_i += GRID_P) {
        const int mBase = mt_i * 128;
        const int validRows = min(128, N_NODES - mBase);

        float d[4][4][4];
#pragma unroll
        for (int i = 0; i < 4; i++)
#pragma unroll
            for (int j = 0; j < 4; j++)
#pragma unroll
                for (int r = 0; r < 4; r++) d[i][j][r] = 0.f;

#pragma unroll
        for (int kt = 0; kt < 2; kt++) {
            const uint32_t BH = kt ? G2_B1H : G2_B0H;
            const uint32_t BL = kt ? G2_B1L : G2_B0L;
            __syncthreads();
            load_tile_async_guard<128>(sbase, G2_AH, sm, g_hh, mBase, validRows,
                                       256, kt * 128, tid);
            load_tile_async_guard<128>(sbase, G2_AL, sm, g_hl, mBase, validRows,
                                       256, kt * 128, tid);
            cp_commit();
            cp_wait0();
            __syncthreads();

#pragma unroll
            for (int k16 = 0; k16 < 8; k16++) {
                uint32_t ah[4][4], al[4][4];
#pragma unroll
                for (int mt = 0; mt < 4; mt++) {
                    int off = (wm * 64 + mt * 16 + aRow) * LDT + k16 * 16 + aK;
                    ldmx4(ah[mt][0], ah[mt][1], ah[mt][2], ah[mt][3],
                          sbase + (G2_AH + off) * 2);
                    ldmx4(al[mt][0], al[mt][1], al[mt][2], al[mt][3],
                          sbase + (G2_AL + off) * 2);
                }
#pragma unroll
                for (int ntp = 0; ntp < 2; ntp++) {
                    int off = (wn * 32 + ntp * 16 + bRowOff) * LDT + k16 * 16 + bKOff;
                    uint32_t bh0, bh1, bh2, bh3, bl0, bl1, bl2, bl3;
                    ldmx4(bh0, bh1, bh2, bh3, sbase + (BH + off) * 2);
                    ldmx4(bl0, bl1, bl2, bl3, sbase + (BL + off) * 2);
#pragma unroll
                    for (int mt = 0; mt < 4; mt++) {
                        mma_bf16(d[mt][2 * ntp],     ah[mt], bh0, bh1);
                        mma_bf16(d[mt][2 * ntp],     ah[mt], bl0, bl1);
                        mma_bf16(d[mt][2 * ntp],     al[mt], bh0, bh1);
                        mma_bf16(d[mt][2 * ntp + 1], ah[mt], bh2, bh3);
                        mma_bf16(d[mt][2 * ntp + 1], ah[mt], bl2, bl3);
                        mma_bf16(d[mt][2 * ntp + 1], al[mt], bh2, bh3);
                    }
                }
            }
        }

#pragma unroll
        for (int mt = 0; mt < 4; mt++) {
            int r0 = mBase + wm * 64 + mt * 16 + (lane >> 2);
#pragma unroll
            for (int nt = 0; nt < 4; nt++) {
                int c0 = wn * 32 + nt * 8 + (lane & 3) * 2;
#pragma unroll
                for (int half = 0; half < 2; half++) {
                    int row = r0 + half * 8;
                    if (row >= N_NODES) continue;
                    *(float2*)(g_h2 + (size_t)row * OUT_DIM + c0) =
                        make_float2(d[mt][nt][half * 2 + 0],
                                    d[mt][nt][half * 2 + 1]);
                }
            }
        }
    }
}

// -------------------------------- launcher ---------------------------------

extern "C" void kernel_launch(void* const* d_in, const int* in_sizes, int n_in,
                              void* d_out, int out_size)
{
    const float* x  = (const float*)d_in[0];
    const void*  ei = d_in[1];
    const float* w  = (const float*)d_in[2];
    const float* W1 = (const float*)d_in[3];
    const float* b1 = (const float*)d_in[4];
    const float* W2 = (const float*)d_in[5];
    const float* b2 = (const float*)d_in[6];
    float* out = (float*)d_out;

    const int aggBlocks = (N_NODES * 32 + 255) / 256;

    cudaFuncSetAttribute(k_gemm1_mma,
        cudaFuncAttributeMaxDynamicSharedMemorySize, G1_SMEM);
    cudaFuncSetAttribute(k_gemm2_mma,
        cudaFuncAttributeMaxDynamicSharedMemorySize, G2_SMEM);

    k_deg_prep<<<EDGE_BLOCKS + PREP_BLOCKS, 256>>>(ei, w, W1, W2);   // 1
    k_scan_fused<<<SCAN_BLOCKS, 1024>>>();                           // 2
    k_place<<<EDGE_BLOCKS, 256>>>(ei, w);                            // 3
    k_agg_in<<<aggBlocks, 256>>>(x);                                 // 4 <- profiled
    k_gemm1_mma<<<GRID_P, 256, G1_SMEM>>>(b1);                       // 5
    k_gemm2_mma<<<GRID_P, 256, G2_SMEM>>>();                         // 6
    k_agg_out<<<aggBlocks, 256>>>(out, b2);                          // 7
}

// round 14
// speedup vs baseline: 2.4685x; 1.1095x over previous
#include <cuda_runtime.h>
#include <cuda_bf16.h>
#include <cstddef>
#include <cstdint>

// ---------------------------------------------------------------------------
// SpatialGCN: 2-layer GCN, N=100000, E=800000, 128 -> 256 -> 128.
//   layer1: relu( agg(x) @ W1 + b1 )   [aggregate BEFORE GEMM, 128-dim]
//   layer2: agg( h @ W2 ) + b2         [aggregate AFTER GEMM, 128-dim]
// FUSED GEMM: one persistent kernel does GEMM1 -> (bias,relu,split) into
// SMEM -> GEMM2, eliminating the 204MB global h round-trip.
// mma.sync m16n8k16 bf16 hi/lo split (AhBh+AhBl+AlBh, fp32 acc).
// ---------------------------------------------------------------------------

#define N_NODES 100000
#define N_EDGES 800000
#define IN_DIM 128
#define HID_DIM 256
#define OUT_DIM 128
#define MTILES ((N_NODES + 127) / 128)     // 782
#define GRID_P 148

typedef __nv_bfloat16 bf16;

#define EDGE_BLOCKS ((N_EDGES + 255) / 256)
#define PREP_ELEMS (IN_DIM * HID_DIM + HID_DIM * OUT_DIM)
#define PREP_BLOCKS ((PREP_ELEMS + 255) / 256)

// -------------------- device scratch (static, no allocs) -------------------
__device__ float g_deg[N_NODES];           // zero at entry; re-zeroed at end
__device__ int   g_cnt[N_NODES];
__device__ float g_dis[N_NODES];
__device__ int   g_off[N_NODES + 1];
__device__ int   g_cur[N_NODES];
__device__ int   g_csr_src[N_EDGES];
__device__ float g_csr_nrm[N_EDGES];

__device__ bf16  g_a1h[(size_t)N_NODES * IN_DIM];
__device__ bf16  g_a1l[(size_t)N_NODES * IN_DIM];
__device__ float g_h2[(size_t)N_NODES * OUT_DIM];

__device__ bf16  g_w1th[HID_DIM * IN_DIM];
__device__ bf16  g_w1tl[HID_DIM * IN_DIM];
__device__ bf16  g_w2th[OUT_DIM * HID_DIM];
__device__ bf16  g_w2tl[OUT_DIM * HID_DIM];

// ------------------------------ PTX helpers --------------------------------

__device__ __forceinline__ uint32_t smem_u32(const void* p)
{
    uint32_t a;
    asm("{ .reg .u64 t; cvta.to.shared.u64 t, %1; cvt.u32.u64 %0, t; }"
        : "=r"(a) : "l"(p));
    return a;
}

__device__ __forceinline__ void cp_async16(uint32_t saddr, const void* gptr)
{
    asm volatile("cp.async.cg.shared.global [%0], [%1], 16;"
                 :: "r"(saddr), "l"(__cvta_generic_to_global(gptr)));
}
__device__ __forceinline__ void cp_commit()
{
    asm volatile("cp.async.commit_group;");
}
__device__ __forceinline__ void cp_wait0()
{
    asm volatile("cp.async.wait_group 0;");
}

__device__ __forceinline__ void ldmx4(uint32_t& r0, uint32_t& r1,
                                      uint32_t& r2, uint32_t& r3, uint32_t a)
{
    asm volatile("ldmatrix.sync.aligned.m8n8.x4.shared.b16 {%0,%1,%2,%3}, [%4];"
                 : "=r"(r0), "=r"(r1), "=r"(r2), "=r"(r3) : "r"(a));
}

__device__ __forceinline__ void mma_bf16(float* d, const uint32_t* a,
                                         uint32_t b0, uint32_t b1)
{
    asm volatile(
        "mma.sync.aligned.m16n8k16.row.col.f32.bf16.bf16.f32 "
        "{%0,%1,%2,%3}, {%4,%5,%6,%7}, {%8,%9}, {%0,%1,%2,%3};"
        : "+f"(d[0]), "+f"(d[1]), "+f"(d[2]), "+f"(d[3])
        : "r"(a[0]), "r"(a[1]), "r"(a[2]), "r"(a[3]), "r"(b0), "r"(b1));
}

__device__ __forceinline__ unsigned short bf_bits(bf16 h)
{
    return *(unsigned short*)&h;
}

// --------------------- per-block edge-dtype detection ----------------------

__device__ __forceinline__ int detect_is64_block(const void* ei)
{
    __shared__ int s_is64;
    int t = threadIdx.x;
    int ok = 1;
    if (t < 16) {
        const long long* p = (const long long*)ei;
        long long a = p[t];
        long long b = p[N_EDGES + t];
        if (a < 0 || a >= N_NODES || b < 0 || b >= N_NODES) ok = 0;
    }
    unsigned bad = __ballot_sync(0xffffffffu, ok == 0);
    if (t == 0) s_is64 = (bad == 0u);
    __syncthreads();
    return s_is64;
}

__device__ __forceinline__ int edge_row(const void* ei, int e, int is64)
{
    if (is64) return (int)((const long long*)ei)[e];
    return ((const int*)ei)[e];
}
__device__ __forceinline__ int edge_col(const void* ei, int e, int is64)
{
    if (is64) return (int)((const long long*)ei)[N_EDGES + e];
    return ((const int*)ei)[N_EDGES + e];
}

// ---------------- launch 1: deg/cnt accumulation + weight prep -------------

__global__ void k_deg_prep(const void* __restrict__ ei,
                           const float* __restrict__ w,
                           const float* __restrict__ W1,
                           const float* __restrict__ W2)
{
    if (blockIdx.x < EDGE_BLOCKS) {
        int is64 = detect_is64_block(ei);
        int e = blockIdx.x * blockDim.x + threadIdx.x;
        if (e >= N_EDGES) return;
        int c = edge_col(ei, e, is64);
        atomicAdd(&g_deg[c], w[e]);
        atomicAdd(&g_cnt[c], 1);
    } else {
        int i = (blockIdx.x - EDGE_BLOCKS) * blockDim.x + threadIdx.x;
        if (i < IN_DIM * HID_DIM) {
            int k = i / HID_DIM, n = i % HID_DIM;
            float v = W1[i];
            bf16 hi = __float2bfloat16(v);
            bf16 lo = __float2bfloat16(v - __bfloat162float(hi));
            g_w1th[n * IN_DIM + k] = hi;
            g_w1tl[n * IN_DIM + k] = lo;
        } else {
            int j = i - IN_DIM * HID_DIM;
            if (j >= HID_DIM * OUT_DIM) return;
            int k = j / OUT_DIM, n = j % OUT_DIM;
            float v = W2[j];
            bf16 hi = __float2bfloat16(v);
            bf16 lo = __float2bfloat16(v - __bfloat162float(hi));
            g_w2th[n * HID_DIM + k] = hi;
            g_w2tl[n * HID_DIM + k] = lo;
        }
    }
}

// -------------- launch 2: fused scan (brute block prefix) + dis ------------
#define SCAN_BLOCKS ((N_NODES + 1023) / 1024)   // 98

__global__ void __launch_bounds__(1024) k_scan_fused()
{
    int b = blockIdx.x, t = threadIdx.x;
    int i = b * 1024 + t;

    int partial = 0;
    {
        const int4* c4 = (const int4*)g_cnt;
        int lim = (b * 1024) >> 2;
        for (int j = t; j < lim; j += 1024) {
            int4 q = c4[j];
            partial += q.x + q.y + q.z + q.w;
        }
    }
#pragma unroll
    for (int o = 16; o > 0; o >>= 1)
        partial += __shfl_down_sync(0xffffffffu, partial, o);
    __shared__ int ws[32];
    __shared__ int s_base;
    if ((t & 31) == 0) ws[t >> 5] = partial;
    __syncthreads();
    if (t < 32) {
        int x = ws[t];
#pragma unroll
        for (int o = 16; o > 0; o >>= 1)
            x += __shfl_down_sync(0xffffffffu, x, o);
        if (t == 0) s_base = x;
    }

    int v = 0;
    if (i < N_NODES) {
        v = g_cnt[i];
        float d = g_deg[i];
        g_dis[i] = (d > 0.f) ? rsqrtf(d) : 0.f;
    }

    int inc = v;
#pragma unroll
    for (int o = 1; o < 32; o <<= 1) {
        int x = __shfl_up_sync(0xffffffffu, inc, o);
        if ((t & 31) >= o) inc += x;
    }
    __shared__ int ws2[32], wo[32];
    if ((t & 31) == 31) ws2[t >> 5] = inc;
    __syncthreads();
    if (t < 32) {
        int x = ws2[t];
        int e = x;
#pragma unroll
        for (int o = 1; o < 32; o <<= 1) {
            int y = __shfl_up_sync(0xffffffffu, e, o);
            if (t >= o) e += y;
        }
        wo[t] = e - x;
    }
    __syncthreads();
    int off = s_base + wo[t >> 5] + inc - v;
    if (i < N_NODES) { g_off[i] = off; g_cur[i] = off; }
    if (b == 0 && t == 0) g_off[N_NODES] = N_EDGES;
}

// --------------------------- launch 3: CSR place ----------------------------

__global__ void k_place(const void* __restrict__ ei,
                        const float* __restrict__ w)
{
    int is64 = detect_is64_block(ei);
    int e = blockIdx.x * blockDim.x + threadIdx.x;
    if (e >= N_EDGES) return;
    int r = edge_row(ei, e, is64);
    int c = edge_col(ei, e, is64);
    float nm = g_dis[r] * w[e] * g_dis[c];
    int pos = atomicAdd(&g_cur[c], 1);
    g_csr_src[pos] = r;
    g_csr_nrm[pos] = nm;
}

// ----------------------------- aggregation ---------------------------------

#define AGG_FMA4(acc, nm, v) \
    do { acc.x = fmaf(nm, v.x, acc.x); acc.y = fmaf(nm, v.y, acc.y); \
         acc.z = fmaf(nm, v.z, acc.z); acc.w = fmaf(nm, v.w, acc.w); } while (0)

__device__ __forceinline__ float4 agg_gather(const float* __restrict__ src,
                                             int beg, int end, int lane)
{
    float4 a0 = make_float4(0.f, 0.f, 0.f, 0.f);
    float4 a1 = make_float4(0.f, 0.f, 0.f, 0.f);
    float4 a2 = make_float4(0.f, 0.f, 0.f, 0.f);
    float4 a3 = make_float4(0.f, 0.f, 0.f, 0.f);
    int e = beg;
    for (; e + 4 <= end; e += 4) {
        int   r0 = g_csr_src[e],     r1 = g_csr_src[e + 1];
        int   r2 = g_csr_src[e + 2], r3 = g_csr_src[e + 3];
        float n0 = g_csr_nrm[e],     n1 = g_csr_nrm[e + 1];
        float n2 = g_csr_nrm[e + 2], n3 = g_csr_nrm[e + 3];
        float4 v0 = __ldg((const float4*)(src + (size_t)r0 * 128 + lane * 4));
        float4 v1 = __ldg((const float4*)(src + (size_t)r1 * 128 + lane * 4));
        float4 v2 = __ldg((const float4*)(src + (size_t)r2 * 128 + lane * 4));
        float4 v3 = __ldg((const float4*)(src + (size_t)r3 * 128 + lane * 4));
        AGG_FMA4(a0, n0, v0); AGG_FMA4(a1, n1, v1);
        AGG_FMA4(a2, n2, v2); AGG_FMA4(a3, n3, v3);
    }
    for (; e < end; e++) {
        int   r0 = g_csr_src[e];
        float n0 = g_csr_nrm[e];
        float4 v0 = __ldg((const float4*)(src + (size_t)r0 * 128 + lane * 4));
        AGG_FMA4(a0, n0, v0);
    }
    return make_float4(a0.x + a1.x + a2.x + a3.x,
                       a0.y + a1.y + a2.y + a3.y,
                       a0.z + a1.z + a2.z + a3.z,
                       a0.w + a1.w + a2.w + a3.w);
}

// launch 4 (profiled slot): agg(x) -> bf16 hi/lo split (one warp per node)
__global__ void k_agg_in(const float* __restrict__ x)
{
    int gw = (blockIdx.x * blockDim.x + threadIdx.x) >> 5;
    if (gw >= N_NODES) return;
    int lane = threadIdx.x & 31;
    float4 acc = agg_gather(x, g_off[gw], g_off[gw + 1], lane);
    bf16 hx = __float2bfloat16(acc.x), hy = __float2bfloat16(acc.y);
    bf16 hz = __float2bfloat16(acc.z), hw = __float2bfloat16(acc.w);
    bf16 lx = __float2bfloat16(acc.x - __bfloat162float(hx));
    bf16 ly = __float2bfloat16(acc.y - __bfloat162float(hy));
    bf16 lz = __float2bfloat16(acc.z - __bfloat162float(hz));
    bf16 lw = __float2bfloat16(acc.w - __bfloat162float(hw));
    size_t o = (size_t)gw * 128 + lane * 4;
    *(ushort4*)(g_a1h + o) = make_ushort4(bf_bits(hx), bf_bits(hy), bf_bits(hz), bf_bits(hw));
    *(ushort4*)(g_a1l + o) = make_ushort4(bf_bits(lx), bf_bits(ly), bf_bits(lz), bf_bits(lw));
}

// launch 6: agg(g_h2) + b2 -> out ; also re-zero g_deg/g_cnt for next run
__global__ void k_agg_out(float* __restrict__ out,
                          const float* __restrict__ b2)
{
    int gt = blockIdx.x * blockDim.x + threadIdx.x;
    if (gt < N_NODES) { g_deg[gt] = 0.f; g_cnt[gt] = 0; }
    int gw = gt >> 5;
    if (gw >= N_NODES) return;
    int lane = threadIdx.x & 31;
    float4 acc = agg_gather(g_h2, g_off[gw], g_off[gw + 1], lane);
    float4 bv = *(const float4*)(b2 + lane * 4);
    acc.x += bv.x; acc.y += bv.y; acc.z += bv.z; acc.w += bv.w;
    *(float4*)(out + (size_t)gw * 128 + lane * 4) = acc;
}

// ----------------------- fused GEMM1+GEMM2 (persistent) ---------------------
// Padded smem rows: LDT=136 elems (272B) for A1/W1/W2, LDT2=264 (528B) for h.
// Both are odd multiples of 16B -> conflict-free ldmatrix.

#define LDT 136
#define LDT2 264

// element offsets into one 104,448-element (208,896 B) pool
#define F_A1H 0
#define F_A1L 17408                 // 128*136
#define F_W1H 34816
#define F_W1L 69632                 // + 256*136
#define F_HH  0                     // h overlays A1/W1 (phase-separated)
#define F_HL  33792                 // 128*264
#define F_W2H 69632                 // W2 halves overlay W1L tail
#define F_W2L 87040
#define FUSED_SMEM (104448 * 2)     // 208896 bytes

template <int ROWS>
__device__ __forceinline__ void load_tile_async_guard(
    uint32_t sbase, uint32_t smo, bf16* smbase_ptr, const bf16* __restrict__ g,
    int rowStart, int validRows, int gStride, int kStart, int tid)
{
#pragma unroll
    for (int it = 0; it < ROWS / 16; it++) {
        int c = it * 256 + tid;
        int r  = c >> 4;
        int cc = c & 15;
        if (r < validRows) {
            uint32_t saddr = sbase + (smo + r * LDT + cc * 8) * 2;
            cp_async16(saddr, g + (size_t)(rowStart + r) * gStride + kStart + cc * 8);
        } else {
            *(uint4*)(smbase_ptr + smo + r * LDT + cc * 8) =
                make_uint4(0u, 0u, 0u, 0u);
        }
    }
}

__global__ void __launch_bounds__(256, 1) k_gcn_fused(const float* __restrict__ b1)
{
    extern __shared__ bf16 sm[];
    const int tid  = threadIdx.x;
    const int lane = tid & 31;
    const int wid  = tid >> 5;
    const int wm   = wid >> 2;          // 0..1
    const int wn   = wid & 3;           // 0..3
    const uint32_t sbase = smem_u32(sm);

    const int aRow = lane & 15;
    const int aK   = (lane >> 4) << 3;
    const int bRowOff = (lane & 7) + (((lane >> 4) & 1) << 3);
    const int bKOff   = (((lane >> 3) & 1) << 3);

    // bias fragment (layer-1 epilogue), loop-invariant
    float bb[8][2];
#pragma unroll
    for (int nt = 0; nt < 8; nt++) {
        int c0 = wn * 64 + nt * 8 + (lane & 3) * 2;
        bb[nt][0] = b1[c0];
        bb[nt][1] = b1[c0 + 1];
    }

    for (int mt_i = blockIdx.x; mt_i < MTILES; mt_i += GRID_P) {
        const int mBase = mt_i * 128;
        const int validRows = min(128, N_NODES - mBase);

        // ---- phase A: load A1 + W1 ----
        __syncthreads();   // protect pool from previous iteration readers
        load_tile_async_guard<128>(sbase, F_A1H, sm, g_a1h, mBase, validRows, 128, 0, tid);
        load_tile_async_guard<128>(sbase, F_A1L, sm, g_a1l, mBase, validRows, 128, 0, tid);
        load_tile_async_guard<256>(sbase, F_W1H, sm, g_w1th, 0, 256, 128, 0, tid);
        load_tile_async_guard<256>(sbase, F_W1L, sm, g_w1tl, 0, 256, 128, 0, tid);
        cp_commit();
        cp_wait0();
        __syncthreads();

        // ---- GEMM1 mainloop: d1[128x256 tile] ----
        float d1[4][8][4];
#pragma unroll
        for (int i = 0; i < 4; i++)
#pragma unroll
            for (int j = 0; j < 8; j++)
#pragma unroll
                for (int r = 0; r < 4; r++) d1[i][j][r] = 0.f;

#pragma unroll
        for (int k16 = 0; k16 < 8; k16++) {
            uint32_t ah[4][4], al[4][4];
#pragma unroll
            for (int mt = 0; mt < 4; mt++) {
                int off = (wm * 64 + mt * 16 + aRow) * LDT + k16 * 16 + aK;
                ldmx4(ah[mt][0], ah[mt][1], ah[mt][2], ah[mt][3],
                      sbase + (F_A1H + off) * 2);
                ldmx4(al[mt][0], al[mt][1], al[mt][2], al[mt][3],
                      sbase + (F_A1L + off) * 2);
            }
#pragma unroll
            for (int ntp = 0; ntp < 4; ntp++) {
                int off = (wn * 64 + ntp * 16 + bRowOff) * LDT + k16 * 16 + bKOff;
                uint32_t bh0, bh1, bh2, bh3, bl0, bl1, bl2, bl3;
                ldmx4(bh0, bh1, bh2, bh3, sbase + (F_W1H + off) * 2);
                ldmx4(bl0, bl1, bl2, bl3, sbase + (F_W1L + off) * 2);
#pragma unroll
                for (int mt = 0; mt < 4; mt++) {
                    mma_bf16(d1[mt][2 * ntp],     ah[mt], bh0, bh1);
                    mma_bf16(d1[mt][2 * ntp],     ah[mt], bl0, bl1);
                    mma_bf16(d1[mt][2 * ntp],     al[mt], bh0, bh1);
                    mma_bf16(d1[mt][2 * ntp + 1], ah[mt], bh2, bh3);
                    mma_bf16(d1[mt][2 * ntp + 1], ah[mt], bl2, bl3);
                    mma_bf16(d1[mt][2 * ntp + 1], al[mt], bh2, bh3);
                }
            }
        }

        __syncthreads();   // everyone done reading A1/W1

        // ---- phase B: prefetch W2 half0, then bias+relu+split -> smem h ----
        load_tile_async_guard<128>(sbase, F_W2H, sm, g_w2th, 0, 128, 256, 0, tid);
        load_tile_async_guard<128>(sbase, F_W2L, sm, g_w2tl, 0, 128, 256, 0, tid);
        cp_commit();

#pragma unroll
        for (int mt = 0; mt < 4; mt++) {
            int r0 = wm * 64 + mt * 16 + (lane >> 2);   // local row in tile
#pragma unroll
            for (int nt = 0; nt < 8; nt++) {
                int c0 = wn * 64 + nt * 8 + (lane & 3) * 2;
#pragma unroll
                for (int half = 0; half < 2; half++) {
                    int row = r0 + half * 8;
                    float v0 = fmaxf(d1[mt][nt][half * 2 + 0] + bb[nt][0], 0.f);
                    float v1 = fmaxf(d1[mt][nt][half * 2 + 1] + bb[nt][1], 0.f);
                    bf16 h0 = __float2bfloat16(v0);
                    bf16 h1 = __float2bfloat16(v1);
                    bf16 l0 = __float2bfloat16(v0 - __bfloat162float(h0));
                    bf16 l1 = __float2bfloat16(v1 - __bfloat162float(h1));
                    *(uint32_t*)(sm + F_HH + row * LDT2 + c0) =
                        (uint32_t)bf_bits(h0) | ((uint32_t)bf_bits(h1) << 16);
                    *(uint32_t*)(sm + F_HL + row * LDT2 + c0) =
                        (uint32_t)bf_bits(l0) | ((uint32_t)bf_bits(l1) << 16);
                }
            }
        }
        cp_wait0();
        __syncthreads();

        // ---- GEMM2: two K-halves from smem h, W2 streamed ----
        float d2[4][4][4];
#pragma unroll
        for (int i = 0; i < 4; i++)
#pragma unroll
            for (int j = 0; j < 4; j++)
#pragma unroll
                for (int r = 0; r < 4; r++) d2[i][j][r] = 0.f;

#pragma unroll
        for (int kt = 0; kt < 2; kt++) {
            if (kt == 1) {
                __syncthreads();   // done reading W2 half0
                load_tile_async_guard<128>(sbase, F_W2H, sm, g_w2th, 0, 128, 256, 128, tid);
                load_tile_async_guard<128>(sbase, F_W2L, sm, g_w2tl, 0, 128, 256, 128, tid);
                cp_commit();
                cp_wait0();
                __syncthreads();
            }
            const int ktStart = kt * 128;
#pragma unroll
            for (int k16 = 0; k16 < 8; k16++) {
                uint32_t ah[4][4], al[4][4];
#pragma unroll
                for (int mt = 0; mt < 4; mt++) {
                    int off = (wm * 64 + mt * 16 + aRow) * LDT2
                            + ktStart + k16 * 16 + aK;
                    ldmx4(ah[mt][0], ah[mt][1], ah[mt][2], ah[mt][3],
                          sbase + (F_HH + off) * 2);
                    ldmx4(al[mt][0], al[mt][1], al[mt][2], al[mt][3],
                          sbase + (F_HL + off) * 2);
                }
#pragma unroll
                for (int ntp = 0; ntp < 2; ntp++) {
                    int off = (wn * 32 + ntp * 16 + bRowOff) * LDT + k16 * 16 + bKOff;
                    uint32_t bh0, bh1, bh2, bh3, bl0, bl1, bl2, bl3;
                    ldmx4(bh0, bh1, bh2, bh3, sbase + (F_W2H + off) * 2);
                    ldmx4(bl0, bl1, bl2, bl3, sbase + (F_W2L + off) * 2);
#pragma unroll
                    for (int mt = 0; mt < 4; mt++) {
                        mma_bf16(d2[mt][2 * ntp],     ah[mt], bh0, bh1);
                        mma_bf16(d2[mt][2 * ntp],     ah[mt], bl0, bl1);
                        mma_bf16(d2[mt][2 * ntp],     al[mt], bh0, bh1);
                        mma_bf16(d2[mt][2 * ntp + 1], ah[mt], bh2, bh3);
                        mma_bf16(d2[mt][2 * ntp + 1], ah[mt], bl2, bl3);
                        mma_bf16(d2[mt][2 * ntp + 1], al[mt], bh2, bh3);
                    }
                }
            }
        }

        // ---- epilogue 2: fp32 -> g_h2 ----
#pragma unroll
        for (int mt = 0; mt < 4; mt++) {
            int r0 = mBase + wm * 64 + mt * 16 + (lane >> 2);
#pragma unroll
            for (int nt = 0; nt < 4; nt++) {
                int c0 = wn * 32 + nt * 8 + (lane & 3) * 2;
#pragma unroll
                for (int half = 0; half < 2; half++) {
                    int row = r0 + half * 8;
                    if (row >= N_NODES) continue;
                    *(float2*)(g_h2 + (size_t)row * OUT_DIM + c0) =
                        make_float2(d2[mt][nt][half * 2 + 0],
                                    d2[mt][nt][half * 2 + 1]);
                }
            }
        }
    }
}

// -------------------------------- launcher ---------------------------------

extern "C" void kernel_launch(void* const* d_in, const int* in_sizes, int n_in,
                              void* d_out, int out_size)
{
    const float* x  = (const float*)d_in[0];
    const void*  ei = d_in[1];
    const float* w  = (const float*)d_in[2];
    const float* W1 = (const float*)d_in[3];
    const float* b1 = (const float*)d_in[4];
    const float* W2 = (const float*)d_in[5];
    const float* b2 = (const float*)d_in[6];
    float* out = (float*)d_out;

    const int aggBlocks = (N_NODES * 32 + 255) / 256;

    cudaFuncSetAttribute(k_gcn_fused,
        cudaFuncAttributeMaxDynamicSharedMemorySize, FUSED_SMEM);

    k_deg_prep<<<EDGE_BLOCKS + PREP_BLOCKS, 256>>>(ei, w, W1, W2);   // 1
    k_scan_fused<<<SCAN_BLOCKS, 1024>>>();                           // 2
    k_place<<<EDGE_BLOCKS, 256>>>(ei, w);                            // 3
    k_agg_in<<<aggBlocks, 256>>>(x);                                 // 4 <- profiled
    k_gcn_fused<<<GRID_P, 256, FUSED_SMEM>>>(b1);                    // 5
    k_agg_out<<<aggBlocks, 256>>>(out, b2);                          // 6
}